// round 1
// baseline (speedup 1.0000x reference)
#include <cuda_runtime.h>
#include <math.h>

// Problem constants
#define BATCH 2
#define NHEAD 16
#define SEQ   2048
#define DMODEL 2048
#define DHEAD 128

// Scratch (allowed: __device__ globals, no runtime allocation)
__device__ float g_Q[(size_t)BATCH * NHEAD * SEQ * DHEAD];   // [B][H][S][DH]
__device__ float g_K[(size_t)BATCH * NHEAD * SEQ * DHEAD];
__device__ float g_V[(size_t)BATCH * NHEAD * SEQ * DHEAD];
__device__ float g_A[(size_t)BATCH * SEQ * DMODEL];          // attn out, [B][S][H*DH]

// ---------------------------------------------------------------------------
// Tiled SGEMM: C[M,N] = A[M,K] @ B[K,N] + bias[N]
// EPI=0: plain store to C.  EPI=1: scatter into g_Q/g_K/g_V per QKV layout.
// Block tile 128x128, K-tile 16, thread tile 8x8, 256 threads.
// ---------------------------------------------------------------------------
template <int EPI>
__global__ void __launch_bounds__(256, 2)
sgemm_kernel(const float* __restrict__ A, const float* __restrict__ Bm,
             const float* __restrict__ bias, float* __restrict__ C,
             int M, int N, int K)
{
    __shared__ float As[16][132];   // transposed A tile, padded (2-way max)
    __shared__ float Bs[16][128];

    const int tid = threadIdx.x;
    const int tx = tid & 15;        // column group
    const int ty = tid >> 4;        // row group
    const int m0 = blockIdx.y * 128;
    const int n0 = blockIdx.x * 128;

    float acc[8][8];
#pragma unroll
    for (int i = 0; i < 8; i++)
#pragma unroll
        for (int j = 0; j < 8; j++) acc[i][j] = 0.0f;

    const float* Aptr = A + (size_t)m0 * K;
    const float* Bptr = Bm + n0;

    for (int k0 = 0; k0 < K; k0 += 16) {
        // Load A tile 128x16, store transposed As[k][m]
#pragma unroll
        for (int r = 0; r < 2; r++) {
            int f = tid + r * 256;          // 0..511 float4s
            int row = f >> 2;               // 0..127
            int col = (f & 3) << 2;         // 0,4,8,12
            float4 a = *(const float4*)(Aptr + (size_t)row * K + k0 + col);
            As[col + 0][row] = a.x;
            As[col + 1][row] = a.y;
            As[col + 2][row] = a.z;
            As[col + 3][row] = a.w;
        }
        // Load B tile 16x128 directly
#pragma unroll
        for (int r = 0; r < 2; r++) {
            int f = tid + r * 256;
            int row = f >> 5;               // 0..15
            int col = (f & 31) << 2;        // 0..124
            *(float4*)&Bs[row][col] =
                *(const float4*)(Bptr + (size_t)(k0 + row) * N + col);
        }
        __syncthreads();

#pragma unroll
        for (int kk = 0; kk < 16; kk++) {
            float ra[8], rb[8];
            float4 a0 = *(const float4*)&As[kk][ty * 8];
            float4 a1 = *(const float4*)&As[kk][ty * 8 + 4];
            ra[0]=a0.x; ra[1]=a0.y; ra[2]=a0.z; ra[3]=a0.w;
            ra[4]=a1.x; ra[5]=a1.y; ra[6]=a1.z; ra[7]=a1.w;
            float4 b0 = *(const float4*)&Bs[kk][tx * 8];
            float4 b1 = *(const float4*)&Bs[kk][tx * 8 + 4];
            rb[0]=b0.x; rb[1]=b0.y; rb[2]=b0.z; rb[3]=b0.w;
            rb[4]=b1.x; rb[5]=b1.y; rb[6]=b1.z; rb[7]=b1.w;
#pragma unroll
            for (int i = 0; i < 8; i++)
#pragma unroll
                for (int j = 0; j < 8; j++)
                    acc[i][j] = fmaf(ra[i], rb[j], acc[i][j]);
        }
        __syncthreads();
    }

    // bias for this thread's 8 columns
    float bv[8];
#pragma unroll
    for (int j = 0; j < 8; j++) bv[j] = bias[n0 + tx * 8 + j];

    if (EPI == 0) {
#pragma unroll
        for (int i = 0; i < 8; i++) {
            int m = m0 + ty * 8 + i;
            float* crow = C + (size_t)m * N + n0 + tx * 8;
            float4 v0, v1;
            v0.x = acc[i][0] + bv[0]; v0.y = acc[i][1] + bv[1];
            v0.z = acc[i][2] + bv[2]; v0.w = acc[i][3] + bv[3];
            v1.x = acc[i][4] + bv[4]; v1.y = acc[i][5] + bv[5];
            v1.z = acc[i][6] + bv[6]; v1.w = acc[i][7] + bv[7];
            *(float4*)crow = v0;
            *(float4*)(crow + 4) = v1;
        }
    } else {
        // QKV scatter: col n = n0 + tx*8 + j; n0 is a multiple of 128 so the
        // whole block maps to one (q/k/v, head) pair.
        int part = n0 >> 11;            // /2048 -> 0:Q 1:K 2:V
        int hh = (n0 & 2047) >> 7;      // head
        float* dst = (part == 0) ? g_Q : (part == 1) ? g_K : g_V;
#pragma unroll
        for (int i = 0; i < 8; i++) {
            int m = m0 + ty * 8 + i;
            int b = m >> 11;            // /SEQ
            int s = m & 2047;
            float* drow = dst + (((size_t)b * NHEAD + hh) * SEQ + s) * DHEAD + tx * 8;
            float4 v0, v1;
            v0.x = acc[i][0] + bv[0]; v0.y = acc[i][1] + bv[1];
            v0.z = acc[i][2] + bv[2]; v0.w = acc[i][3] + bv[3];
            v1.x = acc[i][4] + bv[4]; v1.y = acc[i][5] + bv[5];
            v1.z = acc[i][6] + bv[6]; v1.w = acc[i][7] + bv[7];
            *(float4*)drow = v0;
            *(float4*)(drow + 4) = v1;
        }
    }
}

// ---------------------------------------------------------------------------
// Causal flash attention, fp32.
// Grid: (S/64 q-tiles, B*H). 256 threads (16x16). BQ = BK = 64, DH = 128.
// Thread (ty,tx): rows i = ty*4+ii (both phases), score cols j = tx*4+jj,
// output cols d = tx*8+dd. Row stats (m,l,alpha) live in registers —
// identical row ownership in both phases, so no smem stats and no races.
// ---------------------------------------------------------------------------
#define ATTN_SMEM_FLOATS (128 * 65 + 128 * 65 + 64 * 65)
#define ATTN_SMEM_BYTES (ATTN_SMEM_FLOATS * 4)

__global__ void __launch_bounds__(256, 2)
attn_kernel()
{
    extern __shared__ float smem[];
    float* Qs = smem;                    // [128][65]  transposed: Qs[d][i]
    float* KV = smem + 128 * 65;         // Ks[d][j] (stride 65)  OR  Vs[j][d] (stride 128)
    float* Ps = smem + 2 * 128 * 65;     // [64][65]

    const int tid = threadIdx.x;
    const int tx = tid & 15;
    const int ty = tid >> 4;
    const int qt = blockIdx.x;
    const int bh = blockIdx.y;

    const float* Qb = g_Q + (size_t)bh * SEQ * DHEAD;
    const float* Kb = g_K + (size_t)bh * SEQ * DHEAD;
    const float* Vb = g_V + (size_t)bh * SEQ * DHEAD;
    const int q0 = qt * 64;
    const float scale = 0.088388347648318447f;   // 1/sqrt(128)

    // Load Q tile [64][128] -> transposed Qs[d][i]
#pragma unroll
    for (int r = 0; r < 8; r++) {
        int f = tid + r * 256;          // 0..2047 float4s
        int row = f >> 5;               // 0..63
        int col = (f & 31) << 2;        // 0..124
        float4 v = *(const float4*)(Qb + (size_t)(q0 + row) * DHEAD + col);
        Qs[(col + 0) * 65 + row] = v.x;
        Qs[(col + 1) * 65 + row] = v.y;
        Qs[(col + 2) * 65 + row] = v.z;
        Qs[(col + 3) * 65 + row] = v.w;
    }

    float m_r[4], l_r[4], a_r[4], o_r[4][8];
#pragma unroll
    for (int ii = 0; ii < 4; ii++) {
        m_r[ii] = -1e30f; l_r[ii] = 0.0f;
#pragma unroll
        for (int dd = 0; dd < 8; dd++) o_r[ii][dd] = 0.0f;
    }

    for (int kt = 0; kt <= qt; kt++) {
        const int k0 = kt * 64;
        __syncthreads();   // prior PV reads done / Q tile visible

        // Load K tile transposed: Ks[d][j], stride 65
#pragma unroll
        for (int r = 0; r < 8; r++) {
            int f = tid + r * 256;
            int row = f >> 5;
            int col = (f & 31) << 2;
            float4 v = *(const float4*)(Kb + (size_t)(k0 + row) * DHEAD + col);
            KV[(col + 0) * 65 + row] = v.x;
            KV[(col + 1) * 65 + row] = v.y;
            KV[(col + 2) * 65 + row] = v.z;
            KV[(col + 3) * 65 + row] = v.w;
        }
        __syncthreads();

        // S = Q K^T  (64x64, thread computes 4x4)
        float sacc[4][4];
#pragma unroll
        for (int ii = 0; ii < 4; ii++)
#pragma unroll
            for (int jj = 0; jj < 4; jj++) sacc[ii][jj] = 0.0f;

#pragma unroll 4
        for (int d = 0; d < 128; d++) {
            float qv[4], kv[4];
#pragma unroll
            for (int c = 0; c < 4; c++) qv[c] = Qs[d * 65 + ty * 4 + c];
#pragma unroll
            for (int c = 0; c < 4; c++) kv[c] = KV[d * 65 + tx * 4 + c];
#pragma unroll
            for (int ii = 0; ii < 4; ii++)
#pragma unroll
                for (int jj = 0; jj < 4; jj++)
                    sacc[ii][jj] = fmaf(qv[ii], kv[jj], sacc[ii][jj]);
        }

        const bool diag = (kt == qt);
#pragma unroll
        for (int ii = 0; ii < 4; ii++) {
#pragma unroll
            for (int jj = 0; jj < 4; jj++) {
                float v = sacc[ii][jj] * scale;
                if (diag && (tx * 4 + jj > ty * 4 + ii)) v = -1e30f;
                sacc[ii][jj] = v;
            }
        }

        // Online softmax (rows reduced across the 16 tx lanes = half warp)
#pragma unroll
        for (int ii = 0; ii < 4; ii++) {
            float tmax = fmaxf(fmaxf(sacc[ii][0], sacc[ii][1]),
                               fmaxf(sacc[ii][2], sacc[ii][3]));
#pragma unroll
            for (int off = 8; off >= 1; off >>= 1)
                tmax = fmaxf(tmax, __shfl_xor_sync(0xffffffffu, tmax, off));
            float mnew = fmaxf(m_r[ii], tmax);
            float p0 = __expf(sacc[ii][0] - mnew);
            float p1 = __expf(sacc[ii][1] - mnew);
            float p2 = __expf(sacc[ii][2] - mnew);
            float p3 = __expf(sacc[ii][3] - mnew);
            float rsum = (p0 + p1) + (p2 + p3);
#pragma unroll
            for (int off = 8; off >= 1; off >>= 1)
                rsum += __shfl_xor_sync(0xffffffffu, rsum, off);
            float alpha = __expf(m_r[ii] - mnew);
            a_r[ii] = alpha;
            l_r[ii] = l_r[ii] * alpha + rsum;
            m_r[ii] = mnew;
            int prow = (ty * 4 + ii) * 65 + tx * 4;
            Ps[prow + 0] = p0; Ps[prow + 1] = p1;
            Ps[prow + 2] = p2; Ps[prow + 3] = p3;
        }
        __syncthreads();   // K reads + P writes done

        // Load V tile natural [64][128] (reuses KV buffer)
#pragma unroll
        for (int r = 0; r < 8; r++) {
            int f = tid + r * 256;
            int row = f >> 5;
            int col = (f & 31) << 2;
            *(float4*)&KV[row * 128 + col] =
                *(const float4*)(Vb + (size_t)(k0 + row) * DHEAD + col);
        }
        __syncthreads();

        // O = O*alpha + P V   (thread: rows ty*4+ii, cols tx*8+dd)
#pragma unroll
        for (int ii = 0; ii < 4; ii++) {
            float a = a_r[ii];
#pragma unroll
            for (int dd = 0; dd < 8; dd++) o_r[ii][dd] *= a;
        }
#pragma unroll 4
        for (int j = 0; j < 64; j++) {
            float4 v0 = *(const float4*)&KV[j * 128 + tx * 8];
            float4 v1 = *(const float4*)&KV[j * 128 + tx * 8 + 4];
#pragma unroll
            for (int ii = 0; ii < 4; ii++) {
                float s = Ps[(ty * 4 + ii) * 65 + j];
                o_r[ii][0] = fmaf(s, v0.x, o_r[ii][0]);
                o_r[ii][1] = fmaf(s, v0.y, o_r[ii][1]);
                o_r[ii][2] = fmaf(s, v0.z, o_r[ii][2]);
                o_r[ii][3] = fmaf(s, v0.w, o_r[ii][3]);
                o_r[ii][4] = fmaf(s, v1.x, o_r[ii][4]);
                o_r[ii][5] = fmaf(s, v1.y, o_r[ii][5]);
                o_r[ii][6] = fmaf(s, v1.z, o_r[ii][6]);
                o_r[ii][7] = fmaf(s, v1.w, o_r[ii][7]);
            }
        }
    }

    // Final normalize + store to g_A as [B][S][H][DH]
    const int b = bh >> 4;
    const int h = bh & 15;
#pragma unroll
    for (int ii = 0; ii < 4; ii++) {
        float inv = 1.0f / l_r[ii];
        int s = q0 + ty * 4 + ii;
        float* orow = g_A + (((size_t)b * SEQ + s) * NHEAD + h) * DHEAD + tx * 8;
        float4 v0, v1;
        v0.x = o_r[ii][0] * inv; v0.y = o_r[ii][1] * inv;
        v0.z = o_r[ii][2] * inv; v0.w = o_r[ii][3] * inv;
        v1.x = o_r[ii][4] * inv; v1.y = o_r[ii][5] * inv;
        v1.z = o_r[ii][6] * inv; v1.w = o_r[ii][7] * inv;
        *(float4*)orow = v0;
        *(float4*)(orow + 4) = v1;
    }
}

// ---------------------------------------------------------------------------
extern "C" void kernel_launch(void* const* d_in, const int* in_sizes, int n_in,
                              void* d_out, int out_size)
{
    const float* x     = (const float*)d_in[0];   // [B,S,D]
    const float* Wqkv  = (const float*)d_in[1];   // [D,3D]
    const float* bqkv  = (const float*)d_in[2];   // [3D]
    const float* Wproj = (const float*)d_in[3];   // [D,D]
    const float* bproj = (const float*)d_in[4];   // [D]
    float* out = (float*)d_out;                   // [B,S,D]

    float* gA = nullptr;
    cudaGetSymbolAddress((void**)&gA, g_A);

    dim3 blk(256);

    // 1) QKV projection: [4096,2048] @ [2048,6144] -> scatter into g_Q/g_K/g_V
    sgemm_kernel<1><<<dim3(6144 / 128, 4096 / 128), blk>>>(
        x, Wqkv, bqkv, nullptr, BATCH * SEQ, 3 * DMODEL, DMODEL);

    // 2) Causal flash attention -> g_A [B,S,H*DH]
    cudaFuncSetAttribute(attn_kernel,
                         cudaFuncAttributeMaxDynamicSharedMemorySize,
                         ATTN_SMEM_BYTES);
    attn_kernel<<<dim3(SEQ / 64, BATCH * NHEAD), blk, ATTN_SMEM_BYTES>>>();

    // 3) Output projection: [4096,2048] @ [2048,2048] + bias -> out
    sgemm_kernel<0><<<dim3(2048 / 128, 4096 / 128), blk>>>(
        gA, Wproj, bproj, out, BATCH * SEQ, DMODEL, DMODEL);
}

// round 8
// speedup vs baseline: 1.7182x; 1.7182x over previous
#include <cuda_runtime.h>
#include <cuda_bf16.h>
#include <math.h>
#include <stdint.h>

// Problem constants
#define BATCH 2
#define NHEAD 16
#define SEQ   2048
#define DMODEL 2048
#define DHEAD 128

// ---------------------------------------------------------------------------
// Scratch (__device__ globals: allowed, no runtime allocation)
// ---------------------------------------------------------------------------
__device__ float g_Q[(size_t)BATCH * NHEAD * SEQ * DHEAD];   // [B][H][S][DH]
__device__ float g_K[(size_t)BATCH * NHEAD * SEQ * DHEAD];
__device__ float g_V[(size_t)BATCH * NHEAD * SEQ * DHEAD];
__device__ float g_A[(size_t)BATCH * SEQ * DMODEL];          // attn out [B][S][H*DH]

// bf16 split operands
__device__ __nv_bfloat16 g_xh[(size_t)BATCH * SEQ * DMODEL];     // x hi
__device__ __nv_bfloat16 g_xl[(size_t)BATCH * SEQ * DMODEL];     // x lo
__device__ __nv_bfloat16 g_ah[(size_t)BATCH * SEQ * DMODEL];     // attn-out hi
__device__ __nv_bfloat16 g_al[(size_t)BATCH * SEQ * DMODEL];     // attn-out lo
__device__ __nv_bfloat16 g_wqkvh[(size_t)3 * DMODEL * DMODEL];   // Wqkv^T hi [N][K]
__device__ __nv_bfloat16 g_wqkvl[(size_t)3 * DMODEL * DMODEL];   // Wqkv^T lo
__device__ __nv_bfloat16 g_wprojh[(size_t)DMODEL * DMODEL];      // Wproj^T hi
__device__ __nv_bfloat16 g_wprojl[(size_t)DMODEL * DMODEL];      // Wproj^T lo

// ---------------------------------------------------------------------------
// PTX helpers — ONLY family-generic ISA (compute_103 lowering: no tcgen05!)
// ---------------------------------------------------------------------------
__device__ __forceinline__ uint32_t smem_u32(const void* p) {
    uint32_t a;
    asm("{ .reg .u64 t; cvta.to.shared.u64 t, %1; cvt.u32.u64 %0, t; }"
        : "=r"(a) : "l"(p));
    return a;
}

#define CP_ASYNC16(saddr, gptr) \
    asm volatile("cp.async.ca.shared.global [%0], [%1], 16;" \
                 :: "r"(saddr), "l"(gptr))
#define CP_COMMIT() asm volatile("cp.async.commit_group;")
#define CP_WAIT(n)  asm volatile("cp.async.wait_group %0;" :: "n"(n))

#define LDMATRIX_X4(r0, r1, r2, r3, addr) \
    asm volatile("ldmatrix.sync.aligned.m8n8.x4.shared.b16 {%0,%1,%2,%3}, [%4];" \
                 : "=r"(r0), "=r"(r1), "=r"(r2), "=r"(r3) : "r"(addr))

#define MMA_BF16(d, a, b) \
    asm volatile("mma.sync.aligned.m16n8k16.row.col.f32.bf16.bf16.f32 " \
                 "{%0,%1,%2,%3}, {%4,%5,%6,%7}, {%8,%9}, {%0,%1,%2,%3};" \
                 : "+f"((d)[0]), "+f"((d)[1]), "+f"((d)[2]), "+f"((d)[3]) \
                 : "r"((a)[0]), "r"((a)[1]), "r"((a)[2]), "r"((a)[3]), \
                   "r"((b)[0]), "r"((b)[1]))

// ---------------------------------------------------------------------------
// fp32 -> bf16 hi/lo split (no transpose), vectorized
// ---------------------------------------------------------------------------
__global__ void split_kernel(const float4* __restrict__ in,
                             __nv_bfloat162* __restrict__ hi,
                             __nv_bfloat162* __restrict__ lo, int n4)
{
    int i = blockIdx.x * blockDim.x + threadIdx.x;
    if (i >= n4) return;
    float4 v = in[i];
    __nv_bfloat16 hx = __float2bfloat16(v.x);
    __nv_bfloat16 hy = __float2bfloat16(v.y);
    __nv_bfloat16 hz = __float2bfloat16(v.z);
    __nv_bfloat16 hw = __float2bfloat16(v.w);
    __nv_bfloat162 h0; h0.x = hx; h0.y = hy;
    __nv_bfloat162 h1; h1.x = hz; h1.y = hw;
    __nv_bfloat162 l0, l1;
    l0.x = __float2bfloat16(v.x - __bfloat162float(hx));
    l0.y = __float2bfloat16(v.y - __bfloat162float(hy));
    l1.x = __float2bfloat16(v.z - __bfloat162float(hz));
    l1.y = __float2bfloat16(v.w - __bfloat162float(hw));
    hi[2 * i] = h0; hi[2 * i + 1] = h1;
    lo[2 * i] = l0; lo[2 * i + 1] = l1;
}

// fp32 [R][C] -> bf16 hi/lo transposed [C][R]
__global__ void transpose_split_kernel(const float* __restrict__ in,
                                       __nv_bfloat16* __restrict__ hi,
                                       __nv_bfloat16* __restrict__ lo,
                                       int R, int C)
{
    __shared__ float t[32][33];
    int c0 = blockIdx.x * 32, r0 = blockIdx.y * 32;
    int tx = threadIdx.x, ty = threadIdx.y;
#pragma unroll
    for (int j = 0; j < 32; j += 8)
        t[ty + j][tx] = in[(size_t)(r0 + ty + j) * C + c0 + tx];
    __syncthreads();
#pragma unroll
    for (int j = 0; j < 32; j += 8) {
        float v = t[tx][ty + j];
        __nv_bfloat16 h = __float2bfloat16(v);
        size_t o = (size_t)(c0 + ty + j) * R + r0 + tx;
        hi[o] = h;
        lo[o] = __float2bfloat16(v - __bfloat162float(h));
    }
}

// ---------------------------------------------------------------------------
// Split-bf16 GEMM on mma.sync (HMMA).
// C[M,N] = A[M,K] @ Bt[N,K]^T + bias.  A/Bt bf16 hi/lo pairs, K-major rows.
// D += Ah*Bh + Ah*Bl + Al*Bh (fp32 register accumulators).
// CTA 128x128, 8 warps (2m x 4n), warp tile 64x32 (4x4 m16n8 tiles).
// K-chunk 32, cp.async double buffer. Rows padded to 80B -> conflict-free
// ldmatrix (phases 80*i mod 128 all distinct).
// EPI=0: plain store. EPI=1: QKV scatter to g_Q/g_K/g_V.
// ---------------------------------------------------------------------------
#define MAT_BYTES 10240            // 128 rows * 80B
#define BUF_BYTES (4 * MAT_BYTES)  // Ah, Al, Bh, Bl
#define GM_SMEM_TOTAL (2 * BUF_BYTES)  // 81920

template <int EPI>
__global__ void __launch_bounds__(256)
mma_gemm_kernel(const __nv_bfloat16* __restrict__ Ah,
                const __nv_bfloat16* __restrict__ Al,
                const __nv_bfloat16* __restrict__ Bh,
                const __nv_bfloat16* __restrict__ Bl,
                const float* __restrict__ bias,
                float* __restrict__ C,
                int M, int Nn, int K)
{
    extern __shared__ char smem[];
    const uint32_t sbase = smem_u32(smem);
    const int tid = threadIdx.x;
    const int wid = tid >> 5, lid = tid & 31;
    const int wm = wid >> 2, wn = wid & 3;     // warp grid 2x4
    const int m0 = blockIdx.y * 128;
    const int n0 = blockIdx.x * 128;

    // per-thread gmem/smem load coords (2 iters x 4 matrices per chunk)
    const int ldrow0 = tid >> 2;               // 0..63
    const int ldc16  = tid & 3;                // 16B group within 32-col row
    const uint32_t so0 = (uint32_t)ldrow0 * 80 + ldc16 * 16;
    const uint32_t so1 = (uint32_t)(ldrow0 + 64) * 80 + ldc16 * 16;

    float acc[4][4][4];
#pragma unroll
    for (int i = 0; i < 4; i++)
#pragma unroll
        for (int j = 0; j < 4; j++)
#pragma unroll
            for (int k = 0; k < 4; k++) acc[i][j][k] = 0.0f;

    const int NC = K >> 5;   // 32-wide chunks

    // ---- issue chunk c into buffer c&1 ----
#define ISSUE_CHUNK(c)                                                        \
    do {                                                                      \
        int k0 = (c) << 5;                                                    \
        uint32_t sb = sbase + ((c) & 1) * BUF_BYTES;                          \
        const __nv_bfloat16* gah = Ah + (size_t)(m0 + ldrow0) * K + k0 + ldc16 * 8; \
        const __nv_bfloat16* gal = Al + (size_t)(m0 + ldrow0) * K + k0 + ldc16 * 8; \
        const __nv_bfloat16* gbh = Bh + (size_t)(n0 + ldrow0) * K + k0 + ldc16 * 8; \
        const __nv_bfloat16* gbl = Bl + (size_t)(n0 + ldrow0) * K + k0 + ldc16 * 8; \
        size_t step = (size_t)64 * K;                                         \
        CP_ASYNC16(sb + so0, gah);                                            \
        CP_ASYNC16(sb + so1, gah + step);                                     \
        CP_ASYNC16(sb + MAT_BYTES + so0, gal);                                \
        CP_ASYNC16(sb + MAT_BYTES + so1, gal + step);                         \
        CP_ASYNC16(sb + 2 * MAT_BYTES + so0, gbh);                            \
        CP_ASYNC16(sb + 2 * MAT_BYTES + so1, gbh + step);                     \
        CP_ASYNC16(sb + 3 * MAT_BYTES + so0, gbl);                            \
        CP_ASYNC16(sb + 3 * MAT_BYTES + so1, gbl + step);                     \
        CP_COMMIT();                                                          \
    } while (0)

    ISSUE_CHUNK(0);

    const int grp = lid >> 3;     // ldmatrix lane group 0..3
    const int lr  = lid & 7;

    for (int c = 0; c < NC; c++) {
        if (c + 1 < NC) {
            ISSUE_CHUNK(c + 1);
            CP_WAIT(1);
        } else {
            CP_WAIT(0);
        }
        __syncthreads();

        const uint32_t base = sbase + (c & 1) * BUF_BYTES;
        // A frag row (within CTA tile) for ldmatrix: depends on mt
        // order: m0k0 | m8k0 | m0k8 | m8k8 -> row += (grp&1)*8, kcol += (grp>>1)*8
        const uint32_t a_row_part = (uint32_t)(wm * 64 + lr + (grp & 1) * 8) * 80
                                    + (grp >> 1) * 16;
        // B frag: order n0k0 | n0k8 | n8k0 | n8k8 -> row += (grp>>1)*8, kcol += (grp&1)*8
        const uint32_t b_row_part = (uint32_t)(wn * 32 + lr + (grp >> 1) * 8) * 80
                                    + (grp & 1) * 16;

#pragma unroll
        for (int k16 = 0; k16 < 2; k16++) {
            const uint32_t koff = k16 * 32;   // 16 bf16 = 32B

            // B fragments: 4 n-tiles, hi+lo
            uint32_t bh[4][2], bl[4][2];
#pragma unroll
            for (int j = 0; j < 2; j++) {
                uint32_t addr = base + 2 * MAT_BYTES + b_row_part + j * 16 * 80 + koff;
                LDMATRIX_X4(bh[2 * j][0], bh[2 * j][1],
                            bh[2 * j + 1][0], bh[2 * j + 1][1], addr);
                addr += MAT_BYTES;
                LDMATRIX_X4(bl[2 * j][0], bl[2 * j][1],
                            bl[2 * j + 1][0], bl[2 * j + 1][1], addr);
            }

#pragma unroll
            for (int mt = 0; mt < 4; mt++) {
                uint32_t ah[4], al[4];
                uint32_t addr = base + a_row_part + mt * 16 * 80 + koff;
                LDMATRIX_X4(ah[0], ah[1], ah[2], ah[3], addr);
                addr += MAT_BYTES;
                LDMATRIX_X4(al[0], al[1], al[2], al[3], addr);
#pragma unroll
                for (int nt = 0; nt < 4; nt++) {
                    MMA_BF16(acc[mt][nt], ah, bh[nt]);
                    MMA_BF16(acc[mt][nt], ah, bl[nt]);
                    MMA_BF16(acc[mt][nt], al, bh[nt]);
                }
            }
        }
        __syncthreads();
    }

    // ---- epilogue ----
    const int rbase = m0 + wm * 64 + (lid >> 2);
    const int cbase = n0 + wn * 32 + 2 * (lid & 3);
#pragma unroll
    for (int nt = 0; nt < 4; nt++) {
        const int col = cbase + nt * 8;
        const float b0 = __ldg(&bias[col]);
        const float b1 = __ldg(&bias[col + 1]);
#pragma unroll
        for (int mt = 0; mt < 4; mt++) {
            const int row = rbase + mt * 16;
            float2 v0, v1;
            v0.x = acc[mt][nt][0] + b0; v0.y = acc[mt][nt][1] + b1;
            v1.x = acc[mt][nt][2] + b0; v1.y = acc[mt][nt][3] + b1;
            if (EPI == 0) {
                *(float2*)(C + (size_t)row * Nn + col) = v0;
                *(float2*)(C + (size_t)(row + 8) * Nn + col) = v1;
            } else {
                const int part = col >> 11;
                const int head = (col & 2047) >> 7;
                const int dh0 = col & 127;
                float* dst = (part == 0) ? g_Q : (part == 1) ? g_K : g_V;
                const int bb0 = row >> 11, ss0 = row & 2047;
                *(float2*)(dst + (((size_t)bb0 * NHEAD + head) * SEQ + ss0) * DHEAD + dh0) = v0;
                const int r8 = row + 8;
                const int bb1 = r8 >> 11, ss1 = r8 & 2047;
                *(float2*)(dst + (((size_t)bb1 * NHEAD + head) * SEQ + ss1) * DHEAD + dh0) = v1;
            }
        }
    }
#undef ISSUE_CHUNK
}

// ---------------------------------------------------------------------------
// Causal flash attention, fp32 (unchanged from round 1 — verified correct).
// ---------------------------------------------------------------------------
#define ATTN_SMEM_FLOATS (128 * 65 + 128 * 65 + 64 * 65)
#define ATTN_SMEM_BYTES (ATTN_SMEM_FLOATS * 4)

__global__ void __launch_bounds__(256, 2)
attn_kernel()
{
    extern __shared__ float fsmem[];
    float* Qs = fsmem;                    // [128][65]  transposed: Qs[d][i]
    float* KV = fsmem + 128 * 65;         // Ks[d][j] (65) OR Vs[j][d] (128)
    float* Ps = fsmem + 2 * 128 * 65;     // [64][65]

    const int tid = threadIdx.x;
    const int tx = tid & 15;
    const int ty = tid >> 4;
    const int qt = blockIdx.x;
    const int bh = blockIdx.y;

    const float* Qb = g_Q + (size_t)bh * SEQ * DHEAD;
    const float* Kb = g_K + (size_t)bh * SEQ * DHEAD;
    const float* Vb = g_V + (size_t)bh * SEQ * DHEAD;
    const int q0 = qt * 64;
    const float scale = 0.088388347648318447f;   // 1/sqrt(128)

#pragma unroll
    for (int r = 0; r < 8; r++) {
        int f = tid + r * 256;
        int row = f >> 5;
        int col = (f & 31) << 2;
        float4 v = *(const float4*)(Qb + (size_t)(q0 + row) * DHEAD + col);
        Qs[(col + 0) * 65 + row] = v.x;
        Qs[(col + 1) * 65 + row] = v.y;
        Qs[(col + 2) * 65 + row] = v.z;
        Qs[(col + 3) * 65 + row] = v.w;
    }

    float m_r[4], l_r[4], a_r[4], o_r[4][8];
#pragma unroll
    for (int ii = 0; ii < 4; ii++) {
        m_r[ii] = -1e30f; l_r[ii] = 0.0f;
#pragma unroll
        for (int dd = 0; dd < 8; dd++) o_r[ii][dd] = 0.0f;
    }

    for (int kt = 0; kt <= qt; kt++) {
        const int k0 = kt * 64;
        __syncthreads();

#pragma unroll
        for (int r = 0; r < 8; r++) {
            int f = tid + r * 256;
            int row = f >> 5;
            int col = (f & 31) << 2;
            float4 v = *(const float4*)(Kb + (size_t)(k0 + row) * DHEAD + col);
            KV[(col + 0) * 65 + row] = v.x;
            KV[(col + 1) * 65 + row] = v.y;
            KV[(col + 2) * 65 + row] = v.z;
            KV[(col + 3) * 65 + row] = v.w;
        }
        __syncthreads();

        float sacc[4][4];
#pragma unroll
        for (int ii = 0; ii < 4; ii++)
#pragma unroll
            for (int jj = 0; jj < 4; jj++) sacc[ii][jj] = 0.0f;

#pragma unroll 4
        for (int d = 0; d < 128; d++) {
            float qv[4], kv[4];
#pragma unroll
            for (int c = 0; c < 4; c++) qv[c] = Qs[d * 65 + ty * 4 + c];
#pragma unroll
            for (int c = 0; c < 4; c++) kv[c] = KV[d * 65 + tx * 4 + c];
#pragma unroll
            for (int ii = 0; ii < 4; ii++)
#pragma unroll
                for (int jj = 0; jj < 4; jj++)
                    sacc[ii][jj] = fmaf(qv[ii], kv[jj], sacc[ii][jj]);
        }

        const bool diag = (kt == qt);
#pragma unroll
        for (int ii = 0; ii < 4; ii++) {
#pragma unroll
            for (int jj = 0; jj < 4; jj++) {
                float v = sacc[ii][jj] * scale;
                if (diag && (tx * 4 + jj > ty * 4 + ii)) v = -1e30f;
                sacc[ii][jj] = v;
            }
        }

#pragma unroll
        for (int ii = 0; ii < 4; ii++) {
            float tmax = fmaxf(fmaxf(sacc[ii][0], sacc[ii][1]),
                               fmaxf(sacc[ii][2], sacc[ii][3]));
#pragma unroll
            for (int off = 8; off >= 1; off >>= 1)
                tmax = fmaxf(tmax, __shfl_xor_sync(0xffffffffu, tmax, off));
            float mnew = fmaxf(m_r[ii], tmax);
            float p0 = __expf(sacc[ii][0] - mnew);
            float p1 = __expf(sacc[ii][1] - mnew);
            float p2 = __expf(sacc[ii][2] - mnew);
            float p3 = __expf(sacc[ii][3] - mnew);
            float rsum = (p0 + p1) + (p2 + p3);
#pragma unroll
            for (int off = 8; off >= 1; off >>= 1)
                rsum += __shfl_xor_sync(0xffffffffu, rsum, off);
            float alpha = __expf(m_r[ii] - mnew);
            a_r[ii] = alpha;
            l_r[ii] = l_r[ii] * alpha + rsum;
            m_r[ii] = mnew;
            int prow = (ty * 4 + ii) * 65 + tx * 4;
            Ps[prow + 0] = p0; Ps[prow + 1] = p1;
            Ps[prow + 2] = p2; Ps[prow + 3] = p3;
        }
        __syncthreads();

#pragma unroll
        for (int r = 0; r < 8; r++) {
            int f = tid + r * 256;
            int row = f >> 5;
            int col = (f & 31) << 2;
            *(float4*)&KV[row * 128 + col] =
                *(const float4*)(Vb + (size_t)(k0 + row) * DHEAD + col);
        }
        __syncthreads();

#pragma unroll
        for (int ii = 0; ii < 4; ii++) {
            float a = a_r[ii];
#pragma unroll
            for (int dd = 0; dd < 8; dd++) o_r[ii][dd] *= a;
        }
#pragma unroll 4
        for (int j = 0; j < 64; j++) {
            float4 v0 = *(const float4*)&KV[j * 128 + tx * 8];
            float4 v1 = *(const float4*)&KV[j * 128 + tx * 8 + 4];
#pragma unroll
            for (int ii = 0; ii < 4; ii++) {
                float s = Ps[(ty * 4 + ii) * 65 + j];
                o_r[ii][0] = fmaf(s, v0.x, o_r[ii][0]);
                o_r[ii][1] = fmaf(s, v0.y, o_r[ii][1]);
                o_r[ii][2] = fmaf(s, v0.z, o_r[ii][2]);
                o_r[ii][3] = fmaf(s, v0.w, o_r[ii][3]);
                o_r[ii][4] = fmaf(s, v1.x, o_r[ii][4]);
                o_r[ii][5] = fmaf(s, v1.y, o_r[ii][5]);
                o_r[ii][6] = fmaf(s, v1.z, o_r[ii][6]);
                o_r[ii][7] = fmaf(s, v1.w, o_r[ii][7]);
            }
        }
    }

    const int b = bh >> 4;
    const int h = bh & 15;
#pragma unroll
    for (int ii = 0; ii < 4; ii++) {
        float inv = 1.0f / l_r[ii];
        int s = q0 + ty * 4 + ii;
        float* orow = g_A + (((size_t)b * SEQ + s) * NHEAD + h) * DHEAD + tx * 8;
        float4 v0, v1;
        v0.x = o_r[ii][0] * inv; v0.y = o_r[ii][1] * inv;
        v0.z = o_r[ii][2] * inv; v0.w = o_r[ii][3] * inv;
        v1.x = o_r[ii][4] * inv; v1.y = o_r[ii][5] * inv;
        v1.z = o_r[ii][6] * inv; v1.w = o_r[ii][7] * inv;
        *(float4*)orow = v0;
        *(float4*)(orow + 4) = v1;
    }
}

// ---------------------------------------------------------------------------
extern "C" void kernel_launch(void* const* d_in, const int* in_sizes, int n_in,
                              void* d_out, int out_size)
{
    const float* x     = (const float*)d_in[0];   // [B,S,D]
    const float* Wqkv  = (const float*)d_in[1];   // [D,3D]
    const float* bqkv  = (const float*)d_in[2];   // [3D]
    const float* Wproj = (const float*)d_in[3];   // [D,D]
    const float* bproj = (const float*)d_in[4];   // [D]
    float* out = (float*)d_out;                   // [B,S,D]

    __nv_bfloat16 *xh, *xl, *ah, *al, *wqh, *wql, *wph, *wpl;
    float* gA;
    cudaGetSymbolAddress((void**)&xh, g_xh);
    cudaGetSymbolAddress((void**)&xl, g_xl);
    cudaGetSymbolAddress((void**)&ah, g_ah);
    cudaGetSymbolAddress((void**)&al, g_al);
    cudaGetSymbolAddress((void**)&wqh, g_wqkvh);
    cudaGetSymbolAddress((void**)&wql, g_wqkvl);
    cudaGetSymbolAddress((void**)&wph, g_wprojh);
    cudaGetSymbolAddress((void**)&wpl, g_wprojl);
    cudaGetSymbolAddress((void**)&gA, g_A);

    cudaFuncSetAttribute(mma_gemm_kernel<0>,
                         cudaFuncAttributeMaxDynamicSharedMemorySize, GM_SMEM_TOTAL);
    cudaFuncSetAttribute(mma_gemm_kernel<1>,
                         cudaFuncAttributeMaxDynamicSharedMemorySize, GM_SMEM_TOTAL);
    cudaFuncSetAttribute(attn_kernel,
                         cudaFuncAttributeMaxDynamicSharedMemorySize, ATTN_SMEM_BYTES);

    const int M = BATCH * SEQ;   // 4096

    // 1) split x -> bf16 hi/lo
    {
        int n4 = M * DMODEL / 4;
        split_kernel<<<(n4 + 255) / 256, 256>>>((const float4*)x,
                                                (__nv_bfloat162*)xh,
                                                (__nv_bfloat162*)xl, n4);
    }
    // 2) transpose+split weights
    transpose_split_kernel<<<dim3(3 * DMODEL / 32, DMODEL / 32), dim3(32, 8)>>>(
        Wqkv, wqh, wql, DMODEL, 3 * DMODEL);
    transpose_split_kernel<<<dim3(DMODEL / 32, DMODEL / 32), dim3(32, 8)>>>(
        Wproj, wph, wpl, DMODEL, DMODEL);

    // 3) QKV projection (HMMA) -> scatter fp32 Q/K/V
    mma_gemm_kernel<1><<<dim3(3 * DMODEL / 128, M / 128), 256, GM_SMEM_TOTAL>>>(
        xh, xl, wqh, wql, bqkv, nullptr, M, 3 * DMODEL, DMODEL);

    // 4) causal flash attention -> g_A (fp32)
    attn_kernel<<<dim3(SEQ / 64, BATCH * NHEAD), 256, ATTN_SMEM_BYTES>>>();

    // 5) split attention output
    {
        int n4 = M * DMODEL / 4;
        split_kernel<<<(n4 + 255) / 256, 256>>>((const float4*)gA,
                                                (__nv_bfloat162*)ah,
                                                (__nv_bfloat162*)al, n4);
    }
    // 6) output projection (HMMA)
    mma_gemm_kernel<0><<<dim3(DMODEL / 128, M / 128), 256, GM_SMEM_TOTAL>>>(
        ah, al, wph, wpl, bproj, out, M, DMODEL, DMODEL);
}

// round 13
// speedup vs baseline: 2.7677x; 1.6108x over previous
#include <cuda_runtime.h>
#include <cuda_bf16.h>
#include <math.h>
#include <stdint.h>

// Problem constants
#define BATCH 2
#define NHEAD 16
#define SEQ   2048
#define DMODEL 2048
#define DHEAD 128

// ---------------------------------------------------------------------------
// Scratch (__device__ globals)
// ---------------------------------------------------------------------------
__device__ __nv_bfloat16 g_Qh[(size_t)BATCH * NHEAD * SEQ * DHEAD];  // [B][H][S][DH]
__device__ __nv_bfloat16 g_Ql[(size_t)BATCH * NHEAD * SEQ * DHEAD];
__device__ __nv_bfloat16 g_Kh[(size_t)BATCH * NHEAD * SEQ * DHEAD];
__device__ __nv_bfloat16 g_Kl[(size_t)BATCH * NHEAD * SEQ * DHEAD];
__device__ __nv_bfloat16 g_Vh[(size_t)BATCH * NHEAD * SEQ * DHEAD];
__device__ __nv_bfloat16 g_Vl[(size_t)BATCH * NHEAD * SEQ * DHEAD];

__device__ __nv_bfloat16 g_xh[(size_t)BATCH * SEQ * DMODEL];     // x hi
__device__ __nv_bfloat16 g_xl[(size_t)BATCH * SEQ * DMODEL];     // x lo
__device__ __nv_bfloat16 g_ah[(size_t)BATCH * SEQ * DMODEL];     // attn-out hi
__device__ __nv_bfloat16 g_al[(size_t)BATCH * SEQ * DMODEL];     // attn-out lo
__device__ __nv_bfloat16 g_wqkvh[(size_t)3 * DMODEL * DMODEL];   // Wqkv^T hi [N][K]
__device__ __nv_bfloat16 g_wqkvl[(size_t)3 * DMODEL * DMODEL];   // Wqkv^T lo
__device__ __nv_bfloat16 g_wprojh[(size_t)DMODEL * DMODEL];      // Wproj^T hi
__device__ __nv_bfloat16 g_wprojl[(size_t)DMODEL * DMODEL];      // Wproj^T lo

// ---------------------------------------------------------------------------
// PTX helpers — family-generic ISA only (compute_103 lowering: no tcgen05)
// ---------------------------------------------------------------------------
__device__ __forceinline__ uint32_t smem_u32(const void* p) {
    uint32_t a;
    asm("{ .reg .u64 t; cvta.to.shared.u64 t, %1; cvt.u32.u64 %0, t; }"
        : "=r"(a) : "l"(p));
    return a;
}

#define CP_ASYNC16(saddr, gptr) \
    asm volatile("cp.async.ca.shared.global [%0], [%1], 16;" \
                 :: "r"(saddr), "l"(gptr))
#define CP_COMMIT() asm volatile("cp.async.commit_group;")
#define CP_WAIT(n)  asm volatile("cp.async.wait_group %0;" :: "n"(n))

#define LDMATRIX_X4(r0, r1, r2, r3, addr) \
    asm volatile("ldmatrix.sync.aligned.m8n8.x4.shared.b16 {%0,%1,%2,%3}, [%4];" \
                 : "=r"(r0), "=r"(r1), "=r"(r2), "=r"(r3) : "r"(addr))

#define LDMATRIX_X4_TRANS(r0, r1, r2, r3, addr) \
    asm volatile("ldmatrix.sync.aligned.m8n8.x4.trans.shared.b16 {%0,%1,%2,%3}, [%4];" \
                 : "=r"(r0), "=r"(r1), "=r"(r2), "=r"(r3) : "r"(addr))

#define MMA_BF16(d, a, b) \
    asm volatile("mma.sync.aligned.m16n8k16.row.col.f32.bf16.bf16.f32 " \
                 "{%0,%1,%2,%3}, {%4,%5,%6,%7}, {%8,%9}, {%0,%1,%2,%3};" \
                 : "+f"((d)[0]), "+f"((d)[1]), "+f"((d)[2]), "+f"((d)[3]) \
                 : "r"((a)[0]), "r"((a)[1]), "r"((a)[2]), "r"((a)[3]), \
                   "r"((b)[0]), "r"((b)[1]))

// pack two fp32 into bf16x2 (first arg -> low half, second -> high half)
__device__ __forceinline__ uint32_t packbf(float lo, float hi) {
    uint32_t r;
    asm("cvt.rn.bf16x2.f32 %0, %1, %2;" : "=r"(r) : "f"(hi), "f"(lo));
    return r;
}
__device__ __forceinline__ float bfres(float v) {
    return v - __bfloat162float(__float2bfloat16(v));
}

// ---------------------------------------------------------------------------
// fp32 -> bf16 hi/lo split (no transpose), vectorized
// ---------------------------------------------------------------------------
__global__ void split_kernel(const float4* __restrict__ in,
                             __nv_bfloat162* __restrict__ hi,
                             __nv_bfloat162* __restrict__ lo, int n4)
{
    int i = blockIdx.x * blockDim.x + threadIdx.x;
    if (i >= n4) return;
    float4 v = in[i];
    __nv_bfloat16 hx = __float2bfloat16(v.x);
    __nv_bfloat16 hy = __float2bfloat16(v.y);
    __nv_bfloat16 hz = __float2bfloat16(v.z);
    __nv_bfloat16 hw = __float2bfloat16(v.w);
    __nv_bfloat162 h0; h0.x = hx; h0.y = hy;
    __nv_bfloat162 h1; h1.x = hz; h1.y = hw;
    __nv_bfloat162 l0, l1;
    l0.x = __float2bfloat16(v.x - __bfloat162float(hx));
    l0.y = __float2bfloat16(v.y - __bfloat162float(hy));
    l1.x = __float2bfloat16(v.z - __bfloat162float(hz));
    l1.y = __float2bfloat16(v.w - __bfloat162float(hw));
    hi[2 * i] = h0; hi[2 * i + 1] = h1;
    lo[2 * i] = l0; lo[2 * i + 1] = l1;
}

// fp32 [R][C] -> bf16 hi/lo transposed [C][R]
__global__ void transpose_split_kernel(const float* __restrict__ in,
                                       __nv_bfloat16* __restrict__ hi,
                                       __nv_bfloat16* __restrict__ lo,
                                       int R, int C)
{
    __shared__ float t[32][33];
    int c0 = blockIdx.x * 32, r0 = blockIdx.y * 32;
    int tx = threadIdx.x, ty = threadIdx.y;
#pragma unroll
    for (int j = 0; j < 32; j += 8)
        t[ty + j][tx] = in[(size_t)(r0 + ty + j) * C + c0 + tx];
    __syncthreads();
#pragma unroll
    for (int j = 0; j < 32; j += 8) {
        float v = t[tx][ty + j];
        __nv_bfloat16 h = __float2bfloat16(v);
        size_t o = (size_t)(c0 + ty + j) * R + r0 + tx;
        hi[o] = h;
        lo[o] = __float2bfloat16(v - __bfloat162float(h));
    }
}

// ---------------------------------------------------------------------------
// Split-bf16 GEMM on mma.sync (HMMA).
// C[M,N] = A[M,K] @ Bt[N,K]^T + bias.  A/Bt bf16 hi/lo pairs, K-major rows.
// D += Ah*Bh + Ah*Bl + Al*Bh (fp32 register accumulators).
// CTA 128x128, 8 warps (2m x 4n), warp tile 64x32 (4x4 m16n8 tiles).
// K-chunk 32, cp.async double buffer. Rows padded to 80B -> conflict-free
// ldmatrix (phases 80*i mod 128 all distinct).
// EPI=0: plain fp32 store. EPI=1: bf16 hi/lo QKV scatter.
// ---------------------------------------------------------------------------
#define MAT_BYTES 10240            // 128 rows * 80B
#define BUF_BYTES (4 * MAT_BYTES)  // Ah, Al, Bh, Bl
#define GM_SMEM_TOTAL (2 * BUF_BYTES)  // 81920

template <int EPI>
__global__ void __launch_bounds__(256)
mma_gemm_kernel(const __nv_bfloat16* __restrict__ Ah,
                const __nv_bfloat16* __restrict__ Al,
                const __nv_bfloat16* __restrict__ Bh,
                const __nv_bfloat16* __restrict__ Bl,
                const float* __restrict__ bias,
                float* __restrict__ C,
                int M, int Nn, int K)
{
    extern __shared__ char smem[];
    const uint32_t sbase = smem_u32(smem);
    const int tid = threadIdx.x;
    const int wid = tid >> 5, lid = tid & 31;
    const int wm = wid >> 2, wn = wid & 3;     // warp grid 2x4
    const int m0 = blockIdx.y * 128;
    const int n0 = blockIdx.x * 128;

    const int ldrow0 = tid >> 2;
    const int ldc16  = tid & 3;
    const uint32_t so0 = (uint32_t)ldrow0 * 80 + ldc16 * 16;
    const uint32_t so1 = (uint32_t)(ldrow0 + 64) * 80 + ldc16 * 16;

    float acc[4][4][4];
#pragma unroll
    for (int i = 0; i < 4; i++)
#pragma unroll
        for (int j = 0; j < 4; j++)
#pragma unroll
            for (int k = 0; k < 4; k++) acc[i][j][k] = 0.0f;

    const int NC = K >> 5;

#define ISSUE_CHUNK(c)                                                        \
    do {                                                                      \
        int k0 = (c) << 5;                                                    \
        uint32_t sb = sbase + ((c) & 1) * BUF_BYTES;                          \
        const __nv_bfloat16* gah = Ah + (size_t)(m0 + ldrow0) * K + k0 + ldc16 * 8; \
        const __nv_bfloat16* gal = Al + (size_t)(m0 + ldrow0) * K + k0 + ldc16 * 8; \
        const __nv_bfloat16* gbh = Bh + (size_t)(n0 + ldrow0) * K + k0 + ldc16 * 8; \
        const __nv_bfloat16* gbl = Bl + (size_t)(n0 + ldrow0) * K + k0 + ldc16 * 8; \
        size_t step = (size_t)64 * K;                                         \
        CP_ASYNC16(sb + so0, gah);                                            \
        CP_ASYNC16(sb + so1, gah + step);                                     \
        CP_ASYNC16(sb + MAT_BYTES + so0, gal);                                \
        CP_ASYNC16(sb + MAT_BYTES + so1, gal + step);                         \
        CP_ASYNC16(sb + 2 * MAT_BYTES + so0, gbh);                            \
        CP_ASYNC16(sb + 2 * MAT_BYTES + so1, gbh + step);                     \
        CP_ASYNC16(sb + 3 * MAT_BYTES + so0, gbl);                            \
        CP_ASYNC16(sb + 3 * MAT_BYTES + so1, gbl + step);                     \
        CP_COMMIT();                                                          \
    } while (0)

    ISSUE_CHUNK(0);

    const int grp = lid >> 3;
    const int lr  = lid & 7;

    for (int c = 0; c < NC; c++) {
        if (c + 1 < NC) {
            ISSUE_CHUNK(c + 1);
            CP_WAIT(1);
        } else {
            CP_WAIT(0);
        }
        __syncthreads();

        const uint32_t base = sbase + (c & 1) * BUF_BYTES;
        const uint32_t a_row_part = (uint32_t)(wm * 64 + lr + (grp & 1) * 8) * 80
                                    + (grp >> 1) * 16;
        const uint32_t b_row_part = (uint32_t)(wn * 32 + lr + (grp >> 1) * 8) * 80
                                    + (grp & 1) * 16;

#pragma unroll
        for (int k16 = 0; k16 < 2; k16++) {
            const uint32_t koff = k16 * 32;

            uint32_t bh[4][2], bl[4][2];
#pragma unroll
            for (int j = 0; j < 2; j++) {
                uint32_t addr = base + 2 * MAT_BYTES + b_row_part + j * 16 * 80 + koff;
                LDMATRIX_X4(bh[2 * j][0], bh[2 * j][1],
                            bh[2 * j + 1][0], bh[2 * j + 1][1], addr);
                addr += MAT_BYTES;
                LDMATRIX_X4(bl[2 * j][0], bl[2 * j][1],
                            bl[2 * j + 1][0], bl[2 * j + 1][1], addr);
            }

#pragma unroll
            for (int mt = 0; mt < 4; mt++) {
                uint32_t ah[4], al[4];
                uint32_t addr = base + a_row_part + mt * 16 * 80 + koff;
                LDMATRIX_X4(ah[0], ah[1], ah[2], ah[3], addr);
                addr += MAT_BYTES;
                LDMATRIX_X4(al[0], al[1], al[2], al[3], addr);
#pragma unroll
                for (int nt = 0; nt < 4; nt++) {
                    MMA_BF16(acc[mt][nt], ah, bh[nt]);
                    MMA_BF16(acc[mt][nt], ah, bl[nt]);
                    MMA_BF16(acc[mt][nt], al, bh[nt]);
                }
            }
        }
        __syncthreads();
    }

    // ---- epilogue ----
    const int rbase = m0 + wm * 64 + (lid >> 2);
    const int cbase = n0 + wn * 32 + 2 * (lid & 3);
#pragma unroll
    for (int nt = 0; nt < 4; nt++) {
        const int col = cbase + nt * 8;
        const float b0 = __ldg(&bias[col]);
        const float b1 = __ldg(&bias[col + 1]);
#pragma unroll
        for (int mt = 0; mt < 4; mt++) {
            const int row = rbase + mt * 16;
            float x0 = acc[mt][nt][0] + b0, x1 = acc[mt][nt][1] + b1;
            float y0 = acc[mt][nt][2] + b0, y1 = acc[mt][nt][3] + b1;
            if (EPI == 0) {
                float2 v0, v1;
                v0.x = x0; v0.y = x1; v1.x = y0; v1.y = y1;
                *(float2*)(C + (size_t)row * Nn + col) = v0;
                *(float2*)(C + (size_t)(row + 8) * Nn + col) = v1;
            } else {
                const int part = col >> 11;
                const int head = (col & 2047) >> 7;
                const int dh0 = col & 127;
                __nv_bfloat16* dsth = (part == 0) ? g_Qh : (part == 1) ? g_Kh : g_Vh;
                __nv_bfloat16* dstl = (part == 0) ? g_Ql : (part == 1) ? g_Kl : g_Vl;
                const int bb0 = row >> 11, ss0 = row & 2047;
                size_t i0 = (((size_t)bb0 * NHEAD + head) * SEQ + ss0) * DHEAD + dh0;
                *(uint32_t*)(dsth + i0) = packbf(x0, x1);
                *(uint32_t*)(dstl + i0) = packbf(bfres(x0), bfres(x1));
                const int r8 = row + 8;
                const int bb1 = r8 >> 11, ss1 = r8 & 2047;
                size_t i1 = (((size_t)bb1 * NHEAD + head) * SEQ + ss1) * DHEAD + dh0;
                *(uint32_t*)(dsth + i1) = packbf(y0, y1);
                *(uint32_t*)(dstl + i1) = packbf(bfres(y0), bfres(y1));
            }
        }
    }
#undef ISSUE_CHUNK
}

// ---------------------------------------------------------------------------
// HMMA flash attention, split-bf16 numerics, fp32 softmax.
// CTA: 128 q-rows, 8 warps (16 rows each). BK=64 K/V tiles double-buffered.
// Smem stage: Kh | Kl | Vh | Vl, each [64][128]bf16, 272B pitch.
// ---------------------------------------------------------------------------
#define AT_PITCH 272
#define AT_MAT  (64 * AT_PITCH)     // 17408
#define AT_STAGE (4 * AT_MAT)       // 69632
#define AT_SMEM (2 * AT_STAGE)      // 139264
#define AT_QMAT (128 * AT_PITCH)    // 34816 (Q staging in stage1)

__global__ void __launch_bounds__(256, 1)
attn2_kernel()
{
    extern __shared__ char sm2[];
    const uint32_t sb = smem_u32(sm2);
    const int tid = threadIdx.x;
    const int w = tid >> 5, lid = tid & 31;
    const int qt = blockIdx.x, bh = blockIdx.y;
    const size_t bho = (size_t)bh * SEQ * DHEAD;
    const __nv_bfloat16* Qhp = g_Qh + bho;
    const __nv_bfloat16* Qlp = g_Ql + bho;
    const __nv_bfloat16* Khp = g_Kh + bho;
    const __nv_bfloat16* Klp = g_Kl + bho;
    const __nv_bfloat16* Vhp = g_Vh + bho;
    const __nv_bfloat16* Vlp = g_Vl + bho;
    const float scale = 0.088388347648318447f;   // 1/sqrt(128)

    // stage Q tile [128][128] hi/lo into stage1
    {
        int r_ = tid >> 1;
        size_t g_ = (size_t)(128 * qt + r_) * DHEAD + (tid & 1) * 64;
        uint32_t d_ = sb + AT_STAGE + (uint32_t)r_ * AT_PITCH + (tid & 1) * 128;
#pragma unroll
        for (int i = 0; i < 8; i++) {
            CP_ASYNC16(d_ + i * 16, Qhp + g_ + i * 8);
            CP_ASYNC16(d_ + AT_QMAT + i * 16, Qlp + g_ + i * 8);
        }
        CP_COMMIT();
    }

    // K/V tile issue: 4 threads per row, each thread covers 32 elements (64B)
    // per matrix -> full 128-element rows.
#define ISSUE_KV(ktv, soff)                                                   \
    do {                                                                      \
        int r_ = tid >> 2;                                                    \
        size_t g_ = (size_t)(64 * (ktv) + r_) * DHEAD + (tid & 3) * 32;       \
        uint32_t d_ = (soff) + (uint32_t)r_ * AT_PITCH + (tid & 3) * 64;      \
        CP_ASYNC16(d_,      Khp + g_);                                        \
        CP_ASYNC16(d_ + 16, Khp + g_ + 8);                                    \
        CP_ASYNC16(d_ + 32, Khp + g_ + 16);                                   \
        CP_ASYNC16(d_ + 48, Khp + g_ + 24);                                   \
        CP_ASYNC16(d_ + AT_MAT,      Klp + g_);                               \
        CP_ASYNC16(d_ + AT_MAT + 16, Klp + g_ + 8);                           \
        CP_ASYNC16(d_ + AT_MAT + 32, Klp + g_ + 16);                          \
        CP_ASYNC16(d_ + AT_MAT + 48, Klp + g_ + 24);                          \
        CP_ASYNC16(d_ + 2 * AT_MAT,      Vhp + g_);                           \
        CP_ASYNC16(d_ + 2 * AT_MAT + 16, Vhp + g_ + 8);                       \
        CP_ASYNC16(d_ + 2 * AT_MAT + 32, Vhp + g_ + 16);                      \
        CP_ASYNC16(d_ + 2 * AT_MAT + 48, Vhp + g_ + 24);                      \
        CP_ASYNC16(d_ + 3 * AT_MAT,      Vlp + g_);                           \
        CP_ASYNC16(d_ + 3 * AT_MAT + 16, Vlp + g_ + 8);                       \
        CP_ASYNC16(d_ + 3 * AT_MAT + 32, Vlp + g_ + 16);                      \
        CP_ASYNC16(d_ + 3 * AT_MAT + 48, Vlp + g_ + 24);                      \
        CP_COMMIT();                                                          \
    } while (0)

    ISSUE_KV(0, sb);
    CP_WAIT(1);               // Q staging group done
    __syncthreads();

    // Build Q A-fragments (per warp, rows 16w..16w+15)
    const int lr = lid & 7, grp = lid >> 3;
    uint32_t qh_f[8][4], ql_f[8][4];
    {
        uint32_t ap = sb + AT_STAGE
                      + (uint32_t)(16 * w + lr + (grp & 1) * 8) * AT_PITCH
                      + (grp >> 1) * 16;
#pragma unroll
        for (int kc = 0; kc < 8; kc++) {
            LDMATRIX_X4(qh_f[kc][0], qh_f[kc][1], qh_f[kc][2], qh_f[kc][3],
                        ap + kc * 32);
            LDMATRIX_X4(ql_f[kc][0], ql_f[kc][1], ql_f[kc][2], ql_f[kc][3],
                        ap + AT_QMAT + kc * 32);
        }
    }
    __syncthreads();   // Q reads done; stage1 free for KV

    float o[16][4];
#pragma unroll
    for (int nt = 0; nt < 16; nt++)
#pragma unroll
        for (int k = 0; k < 4; k++) o[nt][k] = 0.0f;
    float m0 = -1e30f, m1 = -1e30f, l0 = 0.0f, l1 = 0.0f;

    const int ktmax = 2 * qt + 1;
    const int q0r = 128 * qt + 16 * w + (lid >> 2);
    const int q1r = q0r + 8;

    for (int kt = 0; kt <= ktmax; kt++) {
        if (kt < ktmax) {
            ISSUE_KV(kt + 1, sb + ((kt + 1) & 1) * AT_STAGE);
            CP_WAIT(1);
        } else {
            CP_WAIT(0);
        }
        __syncthreads();

        const uint32_t kb = sb + (kt & 1) * AT_STAGE;

        // ---- S = Q K^T ----
        float s[8][4];
#pragma unroll
        for (int nt = 0; nt < 8; nt++)
#pragma unroll
            for (int k = 0; k < 4; k++) s[nt][k] = 0.0f;

        const uint32_t kbp = kb + (uint32_t)(lr + (grp >> 1) * 8) * AT_PITCH
                             + (grp & 1) * 16;
#pragma unroll
        for (int kc = 0; kc < 8; kc++) {
#pragma unroll
            for (int t = 0; t < 4; t++) {
                uint32_t kh[4], kl[4];
                uint32_t a_ = kbp + (uint32_t)t * 16 * AT_PITCH + kc * 32;
                LDMATRIX_X4(kh[0], kh[1], kh[2], kh[3], a_);
                LDMATRIX_X4(kl[0], kl[1], kl[2], kl[3], a_ + AT_MAT);
                MMA_BF16(s[2 * t], qh_f[kc], kh);
                MMA_BF16(s[2 * t], qh_f[kc], kl);
                MMA_BF16(s[2 * t], ql_f[kc], kh);
                MMA_BF16(s[2 * t + 1], qh_f[kc], kh + 2);
                MMA_BF16(s[2 * t + 1], qh_f[kc], kl + 2);
                MMA_BF16(s[2 * t + 1], ql_f[kc], kh + 2);
            }
        }

        // ---- scale + causal mask ----
        const bool domask = (kt >= 2 * qt);
        const int scol0 = 64 * kt + 2 * (lid & 3);
        float mx0 = -1e30f, mx1 = -1e30f;
#pragma unroll
        for (int nt = 0; nt < 8; nt++) {
            int c = scol0 + 8 * nt;
            float v0 = s[nt][0] * scale, v1 = s[nt][1] * scale;
            float v2 = s[nt][2] * scale, v3 = s[nt][3] * scale;
            if (domask) {
                if (c > q0r) v0 = -1e30f;
                if (c + 1 > q0r) v1 = -1e30f;
                if (c > q1r) v2 = -1e30f;
                if (c + 1 > q1r) v3 = -1e30f;
            }
            s[nt][0] = v0; s[nt][1] = v1; s[nt][2] = v2; s[nt][3] = v3;
            mx0 = fmaxf(mx0, fmaxf(v0, v1));
            mx1 = fmaxf(mx1, fmaxf(v2, v3));
        }
        mx0 = fmaxf(mx0, __shfl_xor_sync(0xffffffffu, mx0, 1));
        mx0 = fmaxf(mx0, __shfl_xor_sync(0xffffffffu, mx0, 2));
        mx1 = fmaxf(mx1, __shfl_xor_sync(0xffffffffu, mx1, 1));
        mx1 = fmaxf(mx1, __shfl_xor_sync(0xffffffffu, mx1, 2));

        float mn0 = fmaxf(m0, mx0), mn1 = fmaxf(m1, mx1);
        float al0 = __expf(m0 - mn0), al1 = __expf(m1 - mn1);
        m0 = mn0; m1 = mn1;

        float rs0 = 0.0f, rs1 = 0.0f;
#pragma unroll
        for (int nt = 0; nt < 8; nt++) {
            s[nt][0] = __expf(s[nt][0] - mn0); rs0 += s[nt][0];
            s[nt][1] = __expf(s[nt][1] - mn0); rs0 += s[nt][1];
            s[nt][2] = __expf(s[nt][2] - mn1); rs1 += s[nt][2];
            s[nt][3] = __expf(s[nt][3] - mn1); rs1 += s[nt][3];
        }
        rs0 += __shfl_xor_sync(0xffffffffu, rs0, 1);
        rs0 += __shfl_xor_sync(0xffffffffu, rs0, 2);
        rs1 += __shfl_xor_sync(0xffffffffu, rs1, 1);
        rs1 += __shfl_xor_sync(0xffffffffu, rs1, 2);
        l0 = l0 * al0 + rs0;
        l1 = l1 * al1 + rs1;

#pragma unroll
        for (int nt = 0; nt < 16; nt++) {
            o[nt][0] *= al0; o[nt][1] *= al0;
            o[nt][2] *= al1; o[nt][3] *= al1;
        }

        // ---- P fragments (C-frag -> A-frag), bf16 hi/lo ----
        uint32_t pah[4][4], pal[4][4];
#pragma unroll
        for (int kc = 0; kc < 4; kc++) {
            float p00 = s[2 * kc][0], p01 = s[2 * kc][1];
            float p10 = s[2 * kc][2], p11 = s[2 * kc][3];
            float r00 = s[2 * kc + 1][0], r01 = s[2 * kc + 1][1];
            float r10 = s[2 * kc + 1][2], r11 = s[2 * kc + 1][3];
            pah[kc][0] = packbf(p00, p01);
            pah[kc][1] = packbf(p10, p11);
            pah[kc][2] = packbf(r00, r01);
            pah[kc][3] = packbf(r10, r11);
            pal[kc][0] = packbf(bfres(p00), bfres(p01));
            pal[kc][1] = packbf(bfres(p10), bfres(p11));
            pal[kc][2] = packbf(bfres(r00), bfres(r01));
            pal[kc][3] = packbf(bfres(r10), bfres(r11));
        }

        // ---- O += P V  (V via ldmatrix.trans) ----
        const uint32_t vlane = kb + 2 * AT_MAT
                               + (uint32_t)(lid & 15) * AT_PITCH
                               + (lid >> 4) * 16;
#pragma unroll
        for (int kc = 0; kc < 4; kc++) {
#pragma unroll
            for (int tt = 0; tt < 8; tt++) {
                uint32_t vh[4], vl[4];
                uint32_t a_ = vlane + (uint32_t)kc * 16 * AT_PITCH + tt * 32;
                LDMATRIX_X4_TRANS(vh[0], vh[1], vh[2], vh[3], a_);
                MMA_BF16(o[2 * tt], pah[kc], vh);
                MMA_BF16(o[2 * tt], pal[kc], vh);
                MMA_BF16(o[2 * tt + 1], pah[kc], vh + 2);
                MMA_BF16(o[2 * tt + 1], pal[kc], vh + 2);
                LDMATRIX_X4_TRANS(vl[0], vl[1], vl[2], vl[3], a_ + AT_MAT);
                MMA_BF16(o[2 * tt], pah[kc], vl);
                MMA_BF16(o[2 * tt + 1], pah[kc], vl + 2);
            }
        }
        __syncthreads();
    }

    // ---- epilogue: normalize + write bf16 hi/lo attn output ----
    const float inv0 = 1.0f / l0, inv1 = 1.0f / l1;
    const int b_ = bh >> 4, h_ = bh & 15;
    const int s0 = 128 * qt + 16 * w + (lid >> 2);
    const int s1 = s0 + 8;
    const size_t r0o = ((size_t)b_ * SEQ + s0) * DMODEL + h_ * DHEAD + 2 * (lid & 3);
    const size_t r1o = ((size_t)b_ * SEQ + s1) * DMODEL + h_ * DHEAD + 2 * (lid & 3);
#pragma unroll
    for (int nt = 0; nt < 16; nt++) {
        float a0 = o[nt][0] * inv0, a1 = o[nt][1] * inv0;
        float b0 = o[nt][2] * inv1, b1 = o[nt][3] * inv1;
        *(uint32_t*)(g_ah + r0o + 8 * nt) = packbf(a0, a1);
        *(uint32_t*)(g_al + r0o + 8 * nt) = packbf(bfres(a0), bfres(a1));
        *(uint32_t*)(g_ah + r1o + 8 * nt) = packbf(b0, b1);
        *(uint32_t*)(g_al + r1o + 8 * nt) = packbf(bfres(b0), bfres(b1));
    }
#undef ISSUE_KV
}

// ---------------------------------------------------------------------------
extern "C" void kernel_launch(void* const* d_in, const int* in_sizes, int n_in,
                              void* d_out, int out_size)
{
    const float* x     = (const float*)d_in[0];   // [B,S,D]
    const float* Wqkv  = (const float*)d_in[1];   // [D,3D]
    const float* bqkv  = (const float*)d_in[2];   // [3D]
    const float* Wproj = (const float*)d_in[3];   // [D,D]
    const float* bproj = (const float*)d_in[4];   // [D]
    float* out = (float*)d_out;                   // [B,S,D]

    __nv_bfloat16 *xh, *xl, *ah, *al, *wqh, *wql, *wph, *wpl;
    cudaGetSymbolAddress((void**)&xh, g_xh);
    cudaGetSymbolAddress((void**)&xl, g_xl);
    cudaGetSymbolAddress((void**)&ah, g_ah);
    cudaGetSymbolAddress((void**)&al, g_al);
    cudaGetSymbolAddress((void**)&wqh, g_wqkvh);
    cudaGetSymbolAddress((void**)&wql, g_wqkvl);
    cudaGetSymbolAddress((void**)&wph, g_wprojh);
    cudaGetSymbolAddress((void**)&wpl, g_wprojl);

    cudaFuncSetAttribute(mma_gemm_kernel<0>,
                         cudaFuncAttributeMaxDynamicSharedMemorySize, GM_SMEM_TOTAL);
    cudaFuncSetAttribute(mma_gemm_kernel<1>,
                         cudaFuncAttributeMaxDynamicSharedMemorySize, GM_SMEM_TOTAL);
    cudaFuncSetAttribute(attn2_kernel,
                         cudaFuncAttributeMaxDynamicSharedMemorySize, AT_SMEM);

    const int M = BATCH * SEQ;   // 4096

    // 1) split x -> bf16 hi/lo
    {
        int n4 = M * DMODEL / 4;
        split_kernel<<<(n4 + 255) / 256, 256>>>((const float4*)x,
                                                (__nv_bfloat162*)xh,
                                                (__nv_bfloat162*)xl, n4);
    }
    // 2) transpose+split weights
    transpose_split_kernel<<<dim3(3 * DMODEL / 32, DMODEL / 32), dim3(32, 8)>>>(
        Wqkv, wqh, wql, DMODEL, 3 * DMODEL);
    transpose_split_kernel<<<dim3(DMODEL / 32, DMODEL / 32), dim3(32, 8)>>>(
        Wproj, wph, wpl, DMODEL, DMODEL);

    // 3) QKV projection (HMMA) -> bf16 hi/lo Q/K/V
    mma_gemm_kernel<1><<<dim3(3 * DMODEL / 128, M / 128), 256, GM_SMEM_TOTAL>>>(
        xh, xl, wqh, wql, bqkv, nullptr, M, 3 * DMODEL, DMODEL);

    // 4) HMMA flash attention -> g_ah/g_al (bf16 hi/lo)
    attn2_kernel<<<dim3(SEQ / 128, BATCH * NHEAD), 256, AT_SMEM>>>();

    // 5) output projection (HMMA)
    mma_gemm_kernel<0><<<dim3(DMODEL / 128, M / 128), 256, GM_SMEM_TOTAL>>>(
        ah, al, wph, wpl, bproj, out, M, DMODEL, DMODEL);
}

// round 14
// speedup vs baseline: 2.9097x; 1.0513x over previous
#include <cuda_runtime.h>
#include <cuda_bf16.h>
#include <math.h>
#include <stdint.h>

// Problem constants
#define BATCH 2
#define NHEAD 16
#define SEQ   2048
#define DMODEL 2048
#define DHEAD 128

// ---------------------------------------------------------------------------
// Scratch (__device__ globals)
// ---------------------------------------------------------------------------
__device__ __nv_bfloat16 g_Qh[(size_t)BATCH * NHEAD * SEQ * DHEAD];  // [B][H][S][DH]
__device__ __nv_bfloat16 g_Ql[(size_t)BATCH * NHEAD * SEQ * DHEAD];
__device__ __nv_bfloat16 g_Kh[(size_t)BATCH * NHEAD * SEQ * DHEAD];
__device__ __nv_bfloat16 g_Kl[(size_t)BATCH * NHEAD * SEQ * DHEAD];
__device__ __nv_bfloat16 g_Vh[(size_t)BATCH * NHEAD * SEQ * DHEAD];
__device__ __nv_bfloat16 g_Vl[(size_t)BATCH * NHEAD * SEQ * DHEAD];

__device__ __nv_bfloat16 g_xh[(size_t)BATCH * SEQ * DMODEL];     // x hi
__device__ __nv_bfloat16 g_xl[(size_t)BATCH * SEQ * DMODEL];     // x lo
__device__ __nv_bfloat16 g_ah[(size_t)BATCH * SEQ * DMODEL];     // attn-out hi
__device__ __nv_bfloat16 g_al[(size_t)BATCH * SEQ * DMODEL];     // attn-out lo
__device__ __nv_bfloat16 g_wqkvh[(size_t)3 * DMODEL * DMODEL];   // Wqkv^T hi [N][K]
__device__ __nv_bfloat16 g_wqkvl[(size_t)3 * DMODEL * DMODEL];   // Wqkv^T lo
__device__ __nv_bfloat16 g_wprojh[(size_t)DMODEL * DMODEL];      // Wproj^T hi
__device__ __nv_bfloat16 g_wprojl[(size_t)DMODEL * DMODEL];      // Wproj^T lo

// ---------------------------------------------------------------------------
// PTX helpers — family-generic ISA only (compute_103 lowering: no tcgen05)
// ---------------------------------------------------------------------------
__device__ __forceinline__ uint32_t smem_u32(const void* p) {
    uint32_t a;
    asm("{ .reg .u64 t; cvta.to.shared.u64 t, %1; cvt.u32.u64 %0, t; }"
        : "=r"(a) : "l"(p));
    return a;
}

#define CP_ASYNC16(saddr, gptr) \
    asm volatile("cp.async.ca.shared.global [%0], [%1], 16;" \
                 :: "r"(saddr), "l"(gptr))
#define CP_COMMIT() asm volatile("cp.async.commit_group;")
#define CP_WAIT(n)  asm volatile("cp.async.wait_group %0;" :: "n"(n))

#define LDMATRIX_X4(r0, r1, r2, r3, addr) \
    asm volatile("ldmatrix.sync.aligned.m8n8.x4.shared.b16 {%0,%1,%2,%3}, [%4];" \
                 : "=r"(r0), "=r"(r1), "=r"(r2), "=r"(r3) : "r"(addr))

#define LDMATRIX_X4_TRANS(r0, r1, r2, r3, addr) \
    asm volatile("ldmatrix.sync.aligned.m8n8.x4.trans.shared.b16 {%0,%1,%2,%3}, [%4];" \
                 : "=r"(r0), "=r"(r1), "=r"(r2), "=r"(r3) : "r"(addr))

#define MMA_BF16(d, a, b) \
    asm volatile("mma.sync.aligned.m16n8k16.row.col.f32.bf16.bf16.f32 " \
                 "{%0,%1,%2,%3}, {%4,%5,%6,%7}, {%8,%9}, {%0,%1,%2,%3};" \
                 : "+f"((d)[0]), "+f"((d)[1]), "+f"((d)[2]), "+f"((d)[3]) \
                 : "r"((a)[0]), "r"((a)[1]), "r"((a)[2]), "r"((a)[3]), \
                   "r"((b)[0]), "r"((b)[1]))

// pack two fp32 into bf16x2 (first arg -> low half, second -> high half)
__device__ __forceinline__ uint32_t packbf(float lo, float hi) {
    uint32_t r;
    asm("cvt.rn.bf16x2.f32 %0, %1, %2;" : "=r"(r) : "f"(hi), "f"(lo));
    return r;
}
__device__ __forceinline__ float bfres(float v) {
    return v - __bfloat162float(__float2bfloat16(v));
}

// ---------------------------------------------------------------------------
// fp32 -> bf16 hi/lo split (no transpose), vectorized
// ---------------------------------------------------------------------------
__global__ void split_kernel(const float4* __restrict__ in,
                             __nv_bfloat162* __restrict__ hi,
                             __nv_bfloat162* __restrict__ lo, int n4)
{
    int i = blockIdx.x * blockDim.x + threadIdx.x;
    if (i >= n4) return;
    float4 v = in[i];
    __nv_bfloat16 hx = __float2bfloat16(v.x);
    __nv_bfloat16 hy = __float2bfloat16(v.y);
    __nv_bfloat16 hz = __float2bfloat16(v.z);
    __nv_bfloat16 hw = __float2bfloat16(v.w);
    __nv_bfloat162 h0; h0.x = hx; h0.y = hy;
    __nv_bfloat162 h1; h1.x = hz; h1.y = hw;
    __nv_bfloat162 l0, l1;
    l0.x = __float2bfloat16(v.x - __bfloat162float(hx));
    l0.y = __float2bfloat16(v.y - __bfloat162float(hy));
    l1.x = __float2bfloat16(v.z - __bfloat162float(hz));
    l1.y = __float2bfloat16(v.w - __bfloat162float(hw));
    hi[2 * i] = h0; hi[2 * i + 1] = h1;
    lo[2 * i] = l0; lo[2 * i + 1] = l1;
}

// fp32 [R][C] -> bf16 hi/lo transposed [C][R]
__global__ void transpose_split_kernel(const float* __restrict__ in,
                                       __nv_bfloat16* __restrict__ hi,
                                       __nv_bfloat16* __restrict__ lo,
                                       int R, int C)
{
    __shared__ float t[32][33];
    int c0 = blockIdx.x * 32, r0 = blockIdx.y * 32;
    int tx = threadIdx.x, ty = threadIdx.y;
#pragma unroll
    for (int j = 0; j < 32; j += 8)
        t[ty + j][tx] = in[(size_t)(r0 + ty + j) * C + c0 + tx];
    __syncthreads();
#pragma unroll
    for (int j = 0; j < 32; j += 8) {
        float v = t[tx][ty + j];
        __nv_bfloat16 h = __float2bfloat16(v);
        size_t o = (size_t)(c0 + ty + j) * R + r0 + tx;
        hi[o] = h;
        lo[o] = __float2bfloat16(v - __bfloat162float(h));
    }
}

// ---------------------------------------------------------------------------
// Split-bf16 GEMM on mma.sync (HMMA).
// C[M,N] = A[M,K] @ Bt[N,K]^T + bias.  A/Bt bf16 hi/lo pairs, K-major rows.
// D += Ah*Bh + Ah*Bl + Al*Bh (fp32 register accumulators).
// CTA 128x128, 8 warps (2m x 4n), warp tile 64x32 (4x4 m16n8 tiles).
// K-chunk 32, cp.async double buffer. Rows padded to 80B -> conflict-free
// ldmatrix (phases 80*i mod 128 all distinct).
// __launch_bounds__(256, 2): cap regs at 128 so 2 CTAs/SM co-reside
// (smem 80KB x 2 = 160KB < 227KB) — cross-CTA overlap hides fill/barriers.
// EPI=0: plain fp32 store. EPI=1: bf16 hi/lo QKV scatter.
// ---------------------------------------------------------------------------
#define MAT_BYTES 10240            // 128 rows * 80B
#define BUF_BYTES (4 * MAT_BYTES)  // Ah, Al, Bh, Bl
#define GM_SMEM_TOTAL (2 * BUF_BYTES)  // 81920

template <int EPI>
__global__ void __launch_bounds__(256, 2)
mma_gemm_kernel(const __nv_bfloat16* __restrict__ Ah,
                const __nv_bfloat16* __restrict__ Al,
                const __nv_bfloat16* __restrict__ Bh,
                const __nv_bfloat16* __restrict__ Bl,
                const float* __restrict__ bias,
                float* __restrict__ C,
                int M, int Nn, int K)
{
    extern __shared__ char smem[];
    const uint32_t sbase = smem_u32(smem);
    const int tid = threadIdx.x;
    const int wid = tid >> 5, lid = tid & 31;
    const int wm = wid >> 2, wn = wid & 3;     // warp grid 2x4
    const int m0 = blockIdx.y * 128;
    const int n0 = blockIdx.x * 128;

    const int ldrow0 = tid >> 2;
    const int ldc16  = tid & 3;
    const uint32_t so0 = (uint32_t)ldrow0 * 80 + ldc16 * 16;
    const uint32_t so1 = (uint32_t)(ldrow0 + 64) * 80 + ldc16 * 16;

    float acc[4][4][4];
#pragma unroll
    for (int i = 0; i < 4; i++)
#pragma unroll
        for (int j = 0; j < 4; j++)
#pragma unroll
            for (int k = 0; k < 4; k++) acc[i][j][k] = 0.0f;

    const int NC = K >> 5;

#define ISSUE_CHUNK(c)                                                        \
    do {                                                                      \
        int k0 = (c) << 5;                                                    \
        uint32_t sb = sbase + ((c) & 1) * BUF_BYTES;                          \
        const __nv_bfloat16* gah = Ah + (size_t)(m0 + ldrow0) * K + k0 + ldc16 * 8; \
        const __nv_bfloat16* gal = Al + (size_t)(m0 + ldrow0) * K + k0 + ldc16 * 8; \
        const __nv_bfloat16* gbh = Bh + (size_t)(n0 + ldrow0) * K + k0 + ldc16 * 8; \
        const __nv_bfloat16* gbl = Bl + (size_t)(n0 + ldrow0) * K + k0 + ldc16 * 8; \
        size_t step = (size_t)64 * K;                                         \
        CP_ASYNC16(sb + so0, gah);                                            \
        CP_ASYNC16(sb + so1, gah + step);                                     \
        CP_ASYNC16(sb + MAT_BYTES + so0, gal);                                \
        CP_ASYNC16(sb + MAT_BYTES + so1, gal + step);                         \
        CP_ASYNC16(sb + 2 * MAT_BYTES + so0, gbh);                            \
        CP_ASYNC16(sb + 2 * MAT_BYTES + so1, gbh + step);                     \
        CP_ASYNC16(sb + 3 * MAT_BYTES + so0, gbl);                            \
        CP_ASYNC16(sb + 3 * MAT_BYTES + so1, gbl + step);                     \
        CP_COMMIT();                                                          \
    } while (0)

    ISSUE_CHUNK(0);

    const int grp = lid >> 3;
    const int lr  = lid & 7;

    for (int c = 0; c < NC; c++) {
        if (c + 1 < NC) {
            ISSUE_CHUNK(c + 1);
            CP_WAIT(1);
        } else {
            CP_WAIT(0);
        }
        __syncthreads();

        const uint32_t base = sbase + (c & 1) * BUF_BYTES;
        const uint32_t a_row_part = (uint32_t)(wm * 64 + lr + (grp & 1) * 8) * 80
                                    + (grp >> 1) * 16;
        const uint32_t b_row_part = (uint32_t)(wn * 32 + lr + (grp >> 1) * 8) * 80
                                    + (grp & 1) * 16;

#pragma unroll
        for (int k16 = 0; k16 < 2; k16++) {
            const uint32_t koff = k16 * 32;

            uint32_t bh[4][2], bl[4][2];
#pragma unroll
            for (int j = 0; j < 2; j++) {
                uint32_t addr = base + 2 * MAT_BYTES + b_row_part + j * 16 * 80 + koff;
                LDMATRIX_X4(bh[2 * j][0], bh[2 * j][1],
                            bh[2 * j + 1][0], bh[2 * j + 1][1], addr);
                addr += MAT_BYTES;
                LDMATRIX_X4(bl[2 * j][0], bl[2 * j][1],
                            bl[2 * j + 1][0], bl[2 * j + 1][1], addr);
            }

#pragma unroll
            for (int mt = 0; mt < 4; mt++) {
                uint32_t ah[4], al[4];
                uint32_t addr = base + a_row_part + mt * 16 * 80 + koff;
                LDMATRIX_X4(ah[0], ah[1], ah[2], ah[3], addr);
                addr += MAT_BYTES;
                LDMATRIX_X4(al[0], al[1], al[2], al[3], addr);
#pragma unroll
                for (int nt = 0; nt < 4; nt++) {
                    MMA_BF16(acc[mt][nt], ah, bh[nt]);
                    MMA_BF16(acc[mt][nt], ah, bl[nt]);
                    MMA_BF16(acc[mt][nt], al, bh[nt]);
                }
            }
        }
        __syncthreads();
    }

    // ---- epilogue ----
    const int rbase = m0 + wm * 64 + (lid >> 2);
    const int cbase = n0 + wn * 32 + 2 * (lid & 3);
#pragma unroll
    for (int nt = 0; nt < 4; nt++) {
        const int col = cbase + nt * 8;
        const float b0 = __ldg(&bias[col]);
        const float b1 = __ldg(&bias[col + 1]);
#pragma unroll
        for (int mt = 0; mt < 4; mt++) {
            const int row = rbase + mt * 16;
            float x0 = acc[mt][nt][0] + b0, x1 = acc[mt][nt][1] + b1;
            float y0 = acc[mt][nt][2] + b0, y1 = acc[mt][nt][3] + b1;
            if (EPI == 0) {
                float2 v0, v1;
                v0.x = x0; v0.y = x1; v1.x = y0; v1.y = y1;
                *(float2*)(C + (size_t)row * Nn + col) = v0;
                *(float2*)(C + (size_t)(row + 8) * Nn + col) = v1;
            } else {
                const int part = col >> 11;
                const int head = (col & 2047) >> 7;
                const int dh0 = col & 127;
                __nv_bfloat16* dsth = (part == 0) ? g_Qh : (part == 1) ? g_Kh : g_Vh;
                __nv_bfloat16* dstl = (part == 0) ? g_Ql : (part == 1) ? g_Kl : g_Vl;
                const int bb0 = row >> 11, ss0 = row & 2047;
                size_t i0 = (((size_t)bb0 * NHEAD + head) * SEQ + ss0) * DHEAD + dh0;
                *(uint32_t*)(dsth + i0) = packbf(x0, x1);
                *(uint32_t*)(dstl + i0) = packbf(bfres(x0), bfres(x1));
                const int r8 = row + 8;
                const int bb1 = r8 >> 11, ss1 = r8 & 2047;
                size_t i1 = (((size_t)bb1 * NHEAD + head) * SEQ + ss1) * DHEAD + dh0;
                *(uint32_t*)(dsth + i1) = packbf(y0, y1);
                *(uint32_t*)(dstl + i1) = packbf(bfres(y0), bfres(y1));
            }
        }
    }
#undef ISSUE_CHUNK
}

// ---------------------------------------------------------------------------
// HMMA flash attention, split-bf16 numerics, fp32 softmax.
// CTA: 128 q-rows, 8 warps (16 rows each). BK=64 K/V tiles double-buffered.
// Smem stage: Kh | Kl | Vh | Vl, each [64][128]bf16, 272B pitch.
// ---------------------------------------------------------------------------
#define AT_PITCH 272
#define AT_MAT  (64 * AT_PITCH)     // 17408
#define AT_STAGE (4 * AT_MAT)       // 69632
#define AT_SMEM (2 * AT_STAGE)      // 139264
#define AT_QMAT (128 * AT_PITCH)    // 34816 (Q staging in stage1)

__global__ void __launch_bounds__(256, 1)
attn2_kernel()
{
    extern __shared__ char sm2[];
    const uint32_t sb = smem_u32(sm2);
    const int tid = threadIdx.x;
    const int w = tid >> 5, lid = tid & 31;
    const int qt = blockIdx.x, bh = blockIdx.y;
    const size_t bho = (size_t)bh * SEQ * DHEAD;
    const __nv_bfloat16* Qhp = g_Qh + bho;
    const __nv_bfloat16* Qlp = g_Ql + bho;
    const __nv_bfloat16* Khp = g_Kh + bho;
    const __nv_bfloat16* Klp = g_Kl + bho;
    const __nv_bfloat16* Vhp = g_Vh + bho;
    const __nv_bfloat16* Vlp = g_Vl + bho;
    const float scale = 0.088388347648318447f;   // 1/sqrt(128)

    // stage Q tile [128][128] hi/lo into stage1
    {
        int r_ = tid >> 1;
        size_t g_ = (size_t)(128 * qt + r_) * DHEAD + (tid & 1) * 64;
        uint32_t d_ = sb + AT_STAGE + (uint32_t)r_ * AT_PITCH + (tid & 1) * 128;
#pragma unroll
        for (int i = 0; i < 8; i++) {
            CP_ASYNC16(d_ + i * 16, Qhp + g_ + i * 8);
            CP_ASYNC16(d_ + AT_QMAT + i * 16, Qlp + g_ + i * 8);
        }
        CP_COMMIT();
    }

    // K/V tile issue: 4 threads per row, each thread covers 32 elements (64B)
    // per matrix -> full 128-element rows.
#define ISSUE_KV(ktv, soff)                                                   \
    do {                                                                      \
        int r_ = tid >> 2;                                                    \
        size_t g_ = (size_t)(64 * (ktv) + r_) * DHEAD + (tid & 3) * 32;       \
        uint32_t d_ = (soff) + (uint32_t)r_ * AT_PITCH + (tid & 3) * 64;      \
        CP_ASYNC16(d_,      Khp + g_);                                        \
        CP_ASYNC16(d_ + 16, Khp + g_ + 8);                                    \
        CP_ASYNC16(d_ + 32, Khp + g_ + 16);                                   \
        CP_ASYNC16(d_ + 48, Khp + g_ + 24);                                   \
        CP_ASYNC16(d_ + AT_MAT,      Klp + g_);                               \
        CP_ASYNC16(d_ + AT_MAT + 16, Klp + g_ + 8);                           \
        CP_ASYNC16(d_ + AT_MAT + 32, Klp + g_ + 16);                          \
        CP_ASYNC16(d_ + AT_MAT + 48, Klp + g_ + 24);                          \
        CP_ASYNC16(d_ + 2 * AT_MAT,      Vhp + g_);                           \
        CP_ASYNC16(d_ + 2 * AT_MAT + 16, Vhp + g_ + 8);                       \
        CP_ASYNC16(d_ + 2 * AT_MAT + 32, Vhp + g_ + 16);                      \
        CP_ASYNC16(d_ + 2 * AT_MAT + 48, Vhp + g_ + 24);                      \
        CP_ASYNC16(d_ + 3 * AT_MAT,      Vlp + g_);                           \
        CP_ASYNC16(d_ + 3 * AT_MAT + 16, Vlp + g_ + 8);                       \
        CP_ASYNC16(d_ + 3 * AT_MAT + 32, Vlp + g_ + 16);                      \
        CP_ASYNC16(d_ + 3 * AT_MAT + 48, Vlp + g_ + 24);                      \
        CP_COMMIT();                                                          \
    } while (0)

    ISSUE_KV(0, sb);
    CP_WAIT(1);               // Q staging group done
    __syncthreads();

    // Build Q A-fragments (per warp, rows 16w..16w+15)
    const int lr = lid & 7, grp = lid >> 3;
    uint32_t qh_f[8][4], ql_f[8][4];
    {
        uint32_t ap = sb + AT_STAGE
                      + (uint32_t)(16 * w + lr + (grp & 1) * 8) * AT_PITCH
                      + (grp >> 1) * 16;
#pragma unroll
        for (int kc = 0; kc < 8; kc++) {
            LDMATRIX_X4(qh_f[kc][0], qh_f[kc][1], qh_f[kc][2], qh_f[kc][3],
                        ap + kc * 32);
            LDMATRIX_X4(ql_f[kc][0], ql_f[kc][1], ql_f[kc][2], ql_f[kc][3],
                        ap + AT_QMAT + kc * 32);
        }
    }
    __syncthreads();   // Q reads done; stage1 free for KV

    float o[16][4];
#pragma unroll
    for (int nt = 0; nt < 16; nt++)
#pragma unroll
        for (int k = 0; k < 4; k++) o[nt][k] = 0.0f;
    float m0 = -1e30f, m1 = -1e30f, l0 = 0.0f, l1 = 0.0f;

    const int ktmax = 2 * qt + 1;
    const int q0r = 128 * qt + 16 * w + (lid >> 2);
    const int q1r = q0r + 8;

    for (int kt = 0; kt <= ktmax; kt++) {
        if (kt < ktmax) {
            ISSUE_KV(kt + 1, sb + ((kt + 1) & 1) * AT_STAGE);
            CP_WAIT(1);
        } else {
            CP_WAIT(0);
        }
        __syncthreads();

        const uint32_t kb = sb + (kt & 1) * AT_STAGE;

        // ---- S = Q K^T ----
        float s[8][4];
#pragma unroll
        for (int nt = 0; nt < 8; nt++)
#pragma unroll
            for (int k = 0; k < 4; k++) s[nt][k] = 0.0f;

        const uint32_t kbp = kb + (uint32_t)(lr + (grp >> 1) * 8) * AT_PITCH
                             + (grp & 1) * 16;
#pragma unroll
        for (int kc = 0; kc < 8; kc++) {
#pragma unroll
            for (int t = 0; t < 4; t++) {
                uint32_t kh[4], kl[4];
                uint32_t a_ = kbp + (uint32_t)t * 16 * AT_PITCH + kc * 32;
                LDMATRIX_X4(kh[0], kh[1], kh[2], kh[3], a_);
                LDMATRIX_X4(kl[0], kl[1], kl[2], kl[3], a_ + AT_MAT);
                MMA_BF16(s[2 * t], qh_f[kc], kh);
                MMA_BF16(s[2 * t], qh_f[kc], kl);
                MMA_BF16(s[2 * t], ql_f[kc], kh);
                MMA_BF16(s[2 * t + 1], qh_f[kc], kh + 2);
                MMA_BF16(s[2 * t + 1], qh_f[kc], kl + 2);
                MMA_BF16(s[2 * t + 1], ql_f[kc], kh + 2);
            }
        }

        // ---- scale + causal mask ----
        const bool domask = (kt >= 2 * qt);
        const int scol0 = 64 * kt + 2 * (lid & 3);
        float mx0 = -1e30f, mx1 = -1e30f;
#pragma unroll
        for (int nt = 0; nt < 8; nt++) {
            int c = scol0 + 8 * nt;
            float v0 = s[nt][0] * scale, v1 = s[nt][1] * scale;
            float v2 = s[nt][2] * scale, v3 = s[nt][3] * scale;
            if (domask) {
                if (c > q0r) v0 = -1e30f;
                if (c + 1 > q0r) v1 = -1e30f;
                if (c > q1r) v2 = -1e30f;
                if (c + 1 > q1r) v3 = -1e30f;
            }
            s[nt][0] = v0; s[nt][1] = v1; s[nt][2] = v2; s[nt][3] = v3;
            mx0 = fmaxf(mx0, fmaxf(v0, v1));
            mx1 = fmaxf(mx1, fmaxf(v2, v3));
        }
        mx0 = fmaxf(mx0, __shfl_xor_sync(0xffffffffu, mx0, 1));
        mx0 = fmaxf(mx0, __shfl_xor_sync(0xffffffffu, mx0, 2));
        mx1 = fmaxf(mx1, __shfl_xor_sync(0xffffffffu, mx1, 1));
        mx1 = fmaxf(mx1, __shfl_xor_sync(0xffffffffu, mx1, 2));

        float mn0 = fmaxf(m0, mx0), mn1 = fmaxf(m1, mx1);
        float al0 = __expf(m0 - mn0), al1 = __expf(m1 - mn1);
        m0 = mn0; m1 = mn1;

        float rs0 = 0.0f, rs1 = 0.0f;
#pragma unroll
        for (int nt = 0; nt < 8; nt++) {
            s[nt][0] = __expf(s[nt][0] - mn0); rs0 += s[nt][0];
            s[nt][1] = __expf(s[nt][1] - mn0); rs0 += s[nt][1];
            s[nt][2] = __expf(s[nt][2] - mn1); rs1 += s[nt][2];
            s[nt][3] = __expf(s[nt][3] - mn1); rs1 += s[nt][3];
        }
        rs0 += __shfl_xor_sync(0xffffffffu, rs0, 1);
        rs0 += __shfl_xor_sync(0xffffffffu, rs0, 2);
        rs1 += __shfl_xor_sync(0xffffffffu, rs1, 1);
        rs1 += __shfl_xor_sync(0xffffffffu, rs1, 2);
        l0 = l0 * al0 + rs0;
        l1 = l1 * al1 + rs1;

#pragma unroll
        for (int nt = 0; nt < 16; nt++) {
            o[nt][0] *= al0; o[nt][1] *= al0;
            o[nt][2] *= al1; o[nt][3] *= al1;
        }

        // ---- P fragments (C-frag -> A-frag), bf16 hi/lo ----
        uint32_t pah[4][4], pal[4][4];
#pragma unroll
        for (int kc = 0; kc < 4; kc++) {
            float p00 = s[2 * kc][0], p01 = s[2 * kc][1];
            float p10 = s[2 * kc][2], p11 = s[2 * kc][3];
            float r00 = s[2 * kc + 1][0], r01 = s[2 * kc + 1][1];
            float r10 = s[2 * kc + 1][2], r11 = s[2 * kc + 1][3];
            pah[kc][0] = packbf(p00, p01);
            pah[kc][1] = packbf(p10, p11);
            pah[kc][2] = packbf(r00, r01);
            pah[kc][3] = packbf(r10, r11);
            pal[kc][0] = packbf(bfres(p00), bfres(p01));
            pal[kc][1] = packbf(bfres(p10), bfres(p11));
            pal[kc][2] = packbf(bfres(r00), bfres(r01));
            pal[kc][3] = packbf(bfres(r10), bfres(r11));
        }

        // ---- O += P V  (V via ldmatrix.trans) ----
        const uint32_t vlane = kb + 2 * AT_MAT
                               + (uint32_t)(lid & 15) * AT_PITCH
                               + (lid >> 4) * 16;
#pragma unroll
        for (int kc = 0; kc < 4; kc++) {
#pragma unroll
            for (int tt = 0; tt < 8; tt++) {
                uint32_t vh[4], vl[4];
                uint32_t a_ = vlane + (uint32_t)kc * 16 * AT_PITCH + tt * 32;
                LDMATRIX_X4_TRANS(vh[0], vh[1], vh[2], vh[3], a_);
                MMA_BF16(o[2 * tt], pah[kc], vh);
                MMA_BF16(o[2 * tt], pal[kc], vh);
                MMA_BF16(o[2 * tt + 1], pah[kc], vh + 2);
                MMA_BF16(o[2 * tt + 1], pal[kc], vh + 2);
                LDMATRIX_X4_TRANS(vl[0], vl[1], vl[2], vl[3], a_ + AT_MAT);
                MMA_BF16(o[2 * tt], pah[kc], vl);
                MMA_BF16(o[2 * tt + 1], pah[kc], vl + 2);
            }
        }
        __syncthreads();
    }

    // ---- epilogue: normalize + write bf16 hi/lo attn output ----
    const float inv0 = 1.0f / l0, inv1 = 1.0f / l1;
    const int b_ = bh >> 4, h_ = bh & 15;
    const int s0 = 128 * qt + 16 * w + (lid >> 2);
    const int s1 = s0 + 8;
    const size_t r0o = ((size_t)b_ * SEQ + s0) * DMODEL + h_ * DHEAD + 2 * (lid & 3);
    const size_t r1o = ((size_t)b_ * SEQ + s1) * DMODEL + h_ * DHEAD + 2 * (lid & 3);
#pragma unroll
    for (int nt = 0; nt < 16; nt++) {
        float a0 = o[nt][0] * inv0, a1 = o[nt][1] * inv0;
        float b0 = o[nt][2] * inv1, b1 = o[nt][3] * inv1;
        *(uint32_t*)(g_ah + r0o + 8 * nt) = packbf(a0, a1);
        *(uint32_t*)(g_al + r0o + 8 * nt) = packbf(bfres(a0), bfres(a1));
        *(uint32_t*)(g_ah + r1o + 8 * nt) = packbf(b0, b1);
        *(uint32_t*)(g_al + r1o + 8 * nt) = packbf(bfres(b0), bfres(b1));
    }
#undef ISSUE_KV
}

// ---------------------------------------------------------------------------
extern "C" void kernel_launch(void* const* d_in, const int* in_sizes, int n_in,
                              void* d_out, int out_size)
{
    const float* x     = (const float*)d_in[0];   // [B,S,D]
    const float* Wqkv  = (const float*)d_in[1];   // [D,3D]
    const float* bqkv  = (const float*)d_in[2];   // [3D]
    const float* Wproj = (const float*)d_in[3];   // [D,D]
    const float* bproj = (const float*)d_in[4];   // [D]
    float* out = (float*)d_out;                   // [B,S,D]

    __nv_bfloat16 *xh, *xl, *ah, *al, *wqh, *wql, *wph, *wpl;
    cudaGetSymbolAddress((void**)&xh, g_xh);
    cudaGetSymbolAddress((void**)&xl, g_xl);
    cudaGetSymbolAddress((void**)&ah, g_ah);
    cudaGetSymbolAddress((void**)&al, g_al);
    cudaGetSymbolAddress((void**)&wqh, g_wqkvh);
    cudaGetSymbolAddress((void**)&wql, g_wqkvl);
    cudaGetSymbolAddress((void**)&wph, g_wprojh);
    cudaGetSymbolAddress((void**)&wpl, g_wprojl);

    cudaFuncSetAttribute(mma_gemm_kernel<0>,
                         cudaFuncAttributeMaxDynamicSharedMemorySize, GM_SMEM_TOTAL);
    cudaFuncSetAttribute(mma_gemm_kernel<1>,
                         cudaFuncAttributeMaxDynamicSharedMemorySize, GM_SMEM_TOTAL);
    cudaFuncSetAttribute(attn2_kernel,
                         cudaFuncAttributeMaxDynamicSharedMemorySize, AT_SMEM);

    const int M = BATCH * SEQ;   // 4096

    // 1) split x -> bf16 hi/lo
    {
        int n4 = M * DMODEL / 4;
        split_kernel<<<(n4 + 255) / 256, 256>>>((const float4*)x,
                                                (__nv_bfloat162*)xh,
                                                (__nv_bfloat162*)xl, n4);
    }
    // 2) transpose+split weights
    transpose_split_kernel<<<dim3(3 * DMODEL / 32, DMODEL / 32), dim3(32, 8)>>>(
        Wqkv, wqh, wql, DMODEL, 3 * DMODEL);
    transpose_split_kernel<<<dim3(DMODEL / 32, DMODEL / 32), dim3(32, 8)>>>(
        Wproj, wph, wpl, DMODEL, DMODEL);

    // 3) QKV projection (HMMA) -> bf16 hi/lo Q/K/V
    mma_gemm_kernel<1><<<dim3(3 * DMODEL / 128, M / 128), 256, GM_SMEM_TOTAL>>>(
        xh, xl, wqh, wql, bqkv, nullptr, M, 3 * DMODEL, DMODEL);

    // 4) HMMA flash attention -> g_ah/g_al (bf16 hi/lo)
    attn2_kernel<<<dim3(SEQ / 128, BATCH * NHEAD), 256, AT_SMEM>>>();

    // 5) output projection (HMMA)
    mma_gemm_kernel<0><<<dim3(DMODEL / 128, M / 128), 256, GM_SMEM_TOTAL>>>(
        ah, al, wph, wpl, bproj, out, M, DMODEL, DMODEL);
}

// round 15
// speedup vs baseline: 5.8263x; 2.0024x over previous
#include <cuda_runtime.h>
#include <cuda_fp16.h>
#include <math.h>
#include <stdint.h>

// Problem constants
#define BATCH 2
#define NHEAD 16
#define SEQ   2048
#define DMODEL 2048
#define DHEAD 128

// ---------------------------------------------------------------------------
// Scratch (__device__ globals) — single fp16 everywhere
// ---------------------------------------------------------------------------
__device__ __half g_Q[(size_t)BATCH * NHEAD * SEQ * DHEAD];   // [B][H][S][DH]
__device__ __half g_K[(size_t)BATCH * NHEAD * SEQ * DHEAD];
__device__ __half g_V[(size_t)BATCH * NHEAD * SEQ * DHEAD];
__device__ __half g_x[(size_t)BATCH * SEQ * DMODEL];          // x fp16
__device__ __half g_a[(size_t)BATCH * SEQ * DMODEL];          // attn out fp16
__device__ __half g_wqkv[(size_t)3 * DMODEL * DMODEL];        // Wqkv^T [N][K]
__device__ __half g_wproj[(size_t)DMODEL * DMODEL];           // Wproj^T

// ---------------------------------------------------------------------------
// PTX helpers — family-generic ISA only (compute_103 lowering: no tcgen05)
// ---------------------------------------------------------------------------
__device__ __forceinline__ uint32_t smem_u32(const void* p) {
    uint32_t a;
    asm("{ .reg .u64 t; cvta.to.shared.u64 t, %1; cvt.u32.u64 %0, t; }"
        : "=r"(a) : "l"(p));
    return a;
}

#define CP_ASYNC16(saddr, gptr) \
    asm volatile("cp.async.ca.shared.global [%0], [%1], 16;" \
                 :: "r"(saddr), "l"(gptr))
#define CP_COMMIT() asm volatile("cp.async.commit_group;")
#define CP_WAIT(n)  asm volatile("cp.async.wait_group %0;" :: "n"(n))

#define LDMATRIX_X4(r0, r1, r2, r3, addr) \
    asm volatile("ldmatrix.sync.aligned.m8n8.x4.shared.b16 {%0,%1,%2,%3}, [%4];" \
                 : "=r"(r0), "=r"(r1), "=r"(r2), "=r"(r3) : "r"(addr))

#define LDMATRIX_X4_TRANS(r0, r1, r2, r3, addr) \
    asm volatile("ldmatrix.sync.aligned.m8n8.x4.trans.shared.b16 {%0,%1,%2,%3}, [%4];" \
                 : "=r"(r0), "=r"(r1), "=r"(r2), "=r"(r3) : "r"(addr))

#define MMA_F16(d, a, b) \
    asm volatile("mma.sync.aligned.m16n8k16.row.col.f32.f16.f16.f32 " \
                 "{%0,%1,%2,%3}, {%4,%5,%6,%7}, {%8,%9}, {%0,%1,%2,%3};" \
                 : "+f"((d)[0]), "+f"((d)[1]), "+f"((d)[2]), "+f"((d)[3]) \
                 : "r"((a)[0]), "r"((a)[1]), "r"((a)[2]), "r"((a)[3]), \
                   "r"((b)[0]), "r"((b)[1]))

// pack two fp32 into f16x2 (first arg -> low half, second -> high half)
__device__ __forceinline__ uint32_t packh(float lo, float hi) {
    uint32_t r;
    asm("cvt.rn.f16x2.f32 %0, %1, %2;" : "=r"(r) : "f"(hi), "f"(lo));
    return r;
}

// ---------------------------------------------------------------------------
// fp32 -> fp16 convert (vectorized)
// ---------------------------------------------------------------------------
__global__ void convert_kernel(const float4* __restrict__ in,
                               uint2* __restrict__ out, int n4)
{
    int i = blockIdx.x * blockDim.x + threadIdx.x;
    if (i >= n4) return;
    float4 v = in[i];
    uint2 o;
    o.x = packh(v.x, v.y);
    o.y = packh(v.z, v.w);
    out[i] = o;
}

// fp32 [R][C] -> fp16 transposed [C][R]
__global__ void transpose_convert_kernel(const float* __restrict__ in,
                                         __half* __restrict__ out,
                                         int R, int C)
{
    __shared__ float t[32][33];
    int c0 = blockIdx.x * 32, r0 = blockIdx.y * 32;
    int tx = threadIdx.x, ty = threadIdx.y;
#pragma unroll
    for (int j = 0; j < 32; j += 8)
        t[ty + j][tx] = in[(size_t)(r0 + ty + j) * C + c0 + tx];
    __syncthreads();
#pragma unroll
    for (int j = 0; j < 32; j += 8) {
        out[(size_t)(c0 + ty + j) * R + r0 + tx] = __float2half(t[tx][ty + j]);
    }
}

// ---------------------------------------------------------------------------
// fp16 GEMM on mma.sync: C[M,N] = A[M,K] @ Bt[N,K]^T + bias.
// CTA 128x128, 8 warps (2m x 4n), warp tile 64x32. K-chunk 64, double buffer.
// Rows 128B data + 16B pad = 144B pitch -> conflict-free ldmatrix
// (phases 16r mod 128 distinct). __launch_bounds__(256,2): 2 CTAs/SM
// (smem 72KB x 2 = 144KB). EPI=0: fp32 store. EPI=1: fp16 QKV scatter.
// ---------------------------------------------------------------------------
#define MAT_BYTES 18432            // 128 rows * 144B
#define BUF_BYTES (2 * MAT_BYTES)  // A, B
#define GM_SMEM_TOTAL (2 * BUF_BYTES)  // 73728

template <int EPI>
__global__ void __launch_bounds__(256, 2)
mma_gemm_kernel(const __half* __restrict__ A,
                const __half* __restrict__ B,
                const float* __restrict__ bias,
                float* __restrict__ C,
                int M, int Nn, int K)
{
    extern __shared__ char smem[];
    const uint32_t sbase = smem_u32(smem);
    const int tid = threadIdx.x;
    const int wid = tid >> 5, lid = tid & 31;
    const int wm = wid >> 2, wn = wid & 3;     // warp grid 2x4
    const int m0 = blockIdx.y * 128;
    const int n0 = blockIdx.x * 128;

    // loads: 2 threads per 128-row, each covers 64B (4 x cp.async16)
    const int rowA = tid >> 1;
    const int hsel = tid & 1;
    const uint32_t so = (uint32_t)rowA * 144 + hsel * 64;

    float acc[4][4][4];
#pragma unroll
    for (int i = 0; i < 4; i++)
#pragma unroll
        for (int j = 0; j < 4; j++)
#pragma unroll
            for (int k = 0; k < 4; k++) acc[i][j][k] = 0.0f;

    const int NC = K >> 6;   // 64-wide chunks

#define ISSUE_CHUNK(c)                                                        \
    do {                                                                      \
        int k0 = (c) << 6;                                                    \
        uint32_t sb = sbase + ((c) & 1) * BUF_BYTES;                          \
        const __half* ga = A + (size_t)(m0 + rowA) * K + k0 + hsel * 32;      \
        const __half* gb = B + (size_t)(n0 + rowA) * K + k0 + hsel * 32;      \
        CP_ASYNC16(sb + so,      ga);                                         \
        CP_ASYNC16(sb + so + 16, ga + 8);                                     \
        CP_ASYNC16(sb + so + 32, ga + 16);                                    \
        CP_ASYNC16(sb + so + 48, ga + 24);                                    \
        CP_ASYNC16(sb + MAT_BYTES + so,      gb);                             \
        CP_ASYNC16(sb + MAT_BYTES + so + 16, gb + 8);                         \
        CP_ASYNC16(sb + MAT_BYTES + so + 32, gb + 16);                        \
        CP_ASYNC16(sb + MAT_BYTES + so + 48, gb + 24);                        \
        CP_COMMIT();                                                          \
    } while (0)

    ISSUE_CHUNK(0);

    const int grp = lid >> 3;
    const int lr  = lid & 7;

    for (int c = 0; c < NC; c++) {
        if (c + 1 < NC) {
            ISSUE_CHUNK(c + 1);
            CP_WAIT(1);
        } else {
            CP_WAIT(0);
        }
        __syncthreads();

        const uint32_t base = sbase + (c & 1) * BUF_BYTES;
        const uint32_t a_row_part = (uint32_t)(wm * 64 + lr + (grp & 1) * 8) * 144
                                    + (grp >> 1) * 16;
        const uint32_t b_row_part = (uint32_t)(wn * 32 + lr + (grp >> 1) * 8) * 144
                                    + (grp & 1) * 16;

#pragma unroll
        for (int k16 = 0; k16 < 4; k16++) {
            const uint32_t koff = k16 * 32;   // 16 fp16 = 32B

            uint32_t bf[4][2];
#pragma unroll
            for (int j = 0; j < 2; j++) {
                uint32_t addr = base + MAT_BYTES + b_row_part + j * 16 * 144 + koff;
                LDMATRIX_X4(bf[2 * j][0], bf[2 * j][1],
                            bf[2 * j + 1][0], bf[2 * j + 1][1], addr);
            }

#pragma unroll
            for (int mt = 0; mt < 4; mt++) {
                uint32_t af[4];
                uint32_t addr = base + a_row_part + mt * 16 * 144 + koff;
                LDMATRIX_X4(af[0], af[1], af[2], af[3], addr);
#pragma unroll
                for (int nt = 0; nt < 4; nt++) {
                    MMA_F16(acc[mt][nt], af, bf[nt]);
                }
            }
        }
        __syncthreads();
    }

    // ---- epilogue ----
    const int rbase = m0 + wm * 64 + (lid >> 2);
    const int cbase = n0 + wn * 32 + 2 * (lid & 3);
#pragma unroll
    for (int nt = 0; nt < 4; nt++) {
        const int col = cbase + nt * 8;
        const float b0 = __ldg(&bias[col]);
        const float b1 = __ldg(&bias[col + 1]);
#pragma unroll
        for (int mt = 0; mt < 4; mt++) {
            const int row = rbase + mt * 16;
            float x0 = acc[mt][nt][0] + b0, x1 = acc[mt][nt][1] + b1;
            float y0 = acc[mt][nt][2] + b0, y1 = acc[mt][nt][3] + b1;
            if (EPI == 0) {
                float2 v0, v1;
                v0.x = x0; v0.y = x1; v1.x = y0; v1.y = y1;
                *(float2*)(C + (size_t)row * Nn + col) = v0;
                *(float2*)(C + (size_t)(row + 8) * Nn + col) = v1;
            } else {
                const int part = col >> 11;
                const int head = (col & 2047) >> 7;
                const int dh0 = col & 127;
                __half* dst = (part == 0) ? g_Q : (part == 1) ? g_K : g_V;
                const int bb0 = row >> 11, ss0 = row & 2047;
                size_t i0 = (((size_t)bb0 * NHEAD + head) * SEQ + ss0) * DHEAD + dh0;
                *(uint32_t*)(dst + i0) = packh(x0, x1);
                const int r8 = row + 8;
                const int bb1 = r8 >> 11, ss1 = r8 & 2047;
                size_t i1 = (((size_t)bb1 * NHEAD + head) * SEQ + ss1) * DHEAD + dh0;
                *(uint32_t*)(dst + i1) = packh(y0, y1);
            }
        }
    }
#undef ISSUE_CHUNK
}

// ---------------------------------------------------------------------------
// HMMA flash attention, fp16 operands, fp32 softmax.
// CTA: 128 q-rows, 8 warps (16 rows each). BK=64 K/V double-buffered.
// Smem stage: K | V, each [64][128]fp16, 272B pitch. Q staged in stage1.
// ---------------------------------------------------------------------------
#define AT_PITCH 272
#define AT_MAT  (64 * AT_PITCH)     // 17408
#define AT_STAGE (2 * AT_MAT)       // 34816 (K | V)
#define AT_SMEM (2 * AT_STAGE)      // 69632

__global__ void __launch_bounds__(256, 1)
attn2_kernel()
{
    extern __shared__ char sm2[];
    const uint32_t sb = smem_u32(sm2);
    const int tid = threadIdx.x;
    const int w = tid >> 5, lid = tid & 31;
    const int qt = blockIdx.x, bh = blockIdx.y;
    const size_t bho = (size_t)bh * SEQ * DHEAD;
    const __half* Qp = g_Q + bho;
    const __half* Kp = g_K + bho;
    const __half* Vp = g_V + bho;
    const float scale = 0.088388347648318447f;   // 1/sqrt(128)

    // stage Q tile [128][128] fp16 into stage1 (2 threads/row, 128B each)
    {
        int r_ = tid >> 1;
        size_t g_ = (size_t)(128 * qt + r_) * DHEAD + (tid & 1) * 64;
        uint32_t d_ = sb + AT_STAGE + (uint32_t)r_ * AT_PITCH + (tid & 1) * 128;
#pragma unroll
        for (int i = 0; i < 8; i++)
            CP_ASYNC16(d_ + i * 16, Qp + g_ + i * 8);
        CP_COMMIT();
    }

    // K/V tile: 4 threads/row, each 64B per matrix (full 256B rows)
#define ISSUE_KV(ktv, soff)                                                   \
    do {                                                                      \
        int r_ = tid >> 2;                                                    \
        size_t g_ = (size_t)(64 * (ktv) + r_) * DHEAD + (tid & 3) * 32;       \
        uint32_t d_ = (soff) + (uint32_t)r_ * AT_PITCH + (tid & 3) * 64;      \
        CP_ASYNC16(d_,      Kp + g_);                                         \
        CP_ASYNC16(d_ + 16, Kp + g_ + 8);                                     \
        CP_ASYNC16(d_ + 32, Kp + g_ + 16);                                    \
        CP_ASYNC16(d_ + 48, Kp + g_ + 24);                                    \
        CP_ASYNC16(d_ + AT_MAT,      Vp + g_);                                \
        CP_ASYNC16(d_ + AT_MAT + 16, Vp + g_ + 8);                            \
        CP_ASYNC16(d_ + AT_MAT + 32, Vp + g_ + 16);                           \
        CP_ASYNC16(d_ + AT_MAT + 48, Vp + g_ + 24);                           \
        CP_COMMIT();                                                          \
    } while (0)

    ISSUE_KV(0, sb);
    CP_WAIT(1);               // Q staging group done
    __syncthreads();

    // Build Q A-fragments (per warp, rows 16w..16w+15)
    const int lr = lid & 7, grp = lid >> 3;
    uint32_t qf[8][4];
    {
        uint32_t ap = sb + AT_STAGE
                      + (uint32_t)(16 * w + lr + (grp & 1) * 8) * AT_PITCH
                      + (grp >> 1) * 16;
#pragma unroll
        for (int kc = 0; kc < 8; kc++)
            LDMATRIX_X4(qf[kc][0], qf[kc][1], qf[kc][2], qf[kc][3],
                        ap + kc * 32);
    }
    __syncthreads();   // Q reads done; stage1 free for KV

    float o[16][4];
#pragma unroll
    for (int nt = 0; nt < 16; nt++)
#pragma unroll
        for (int k = 0; k < 4; k++) o[nt][k] = 0.0f;
    float m0 = -1e30f, m1 = -1e30f, l0 = 0.0f, l1 = 0.0f;

    const int ktmax = 2 * qt + 1;
    const int q0r = 128 * qt + 16 * w + (lid >> 2);
    const int q1r = q0r + 8;

    for (int kt = 0; kt <= ktmax; kt++) {
        if (kt < ktmax) {
            ISSUE_KV(kt + 1, sb + ((kt + 1) & 1) * AT_STAGE);
            CP_WAIT(1);
        } else {
            CP_WAIT(0);
        }
        __syncthreads();

        const uint32_t kb = sb + (kt & 1) * AT_STAGE;

        // ---- S = Q K^T ----
        float s[8][4];
#pragma unroll
        for (int nt = 0; nt < 8; nt++)
#pragma unroll
            for (int k = 0; k < 4; k++) s[nt][k] = 0.0f;

        const uint32_t kbp = kb + (uint32_t)(lr + (grp >> 1) * 8) * AT_PITCH
                             + (grp & 1) * 16;
#pragma unroll
        for (int kc = 0; kc < 8; kc++) {
#pragma unroll
            for (int t = 0; t < 4; t++) {
                uint32_t kh[4];
                uint32_t a_ = kbp + (uint32_t)t * 16 * AT_PITCH + kc * 32;
                LDMATRIX_X4(kh[0], kh[1], kh[2], kh[3], a_);
                MMA_F16(s[2 * t], qf[kc], kh);
                MMA_F16(s[2 * t + 1], qf[kc], kh + 2);
            }
        }

        // ---- scale + causal mask ----
        const bool domask = (kt >= 2 * qt);
        const int scol0 = 64 * kt + 2 * (lid & 3);
        float mx0 = -1e30f, mx1 = -1e30f;
#pragma unroll
        for (int nt = 0; nt < 8; nt++) {
            int c = scol0 + 8 * nt;
            float v0 = s[nt][0] * scale, v1 = s[nt][1] * scale;
            float v2 = s[nt][2] * scale, v3 = s[nt][3] * scale;
            if (domask) {
                if (c > q0r) v0 = -1e30f;
                if (c + 1 > q0r) v1 = -1e30f;
                if (c > q1r) v2 = -1e30f;
                if (c + 1 > q1r) v3 = -1e30f;
            }
            s[nt][0] = v0; s[nt][1] = v1; s[nt][2] = v2; s[nt][3] = v3;
            mx0 = fmaxf(mx0, fmaxf(v0, v1));
            mx1 = fmaxf(mx1, fmaxf(v2, v3));
        }
        mx0 = fmaxf(mx0, __shfl_xor_sync(0xffffffffu, mx0, 1));
        mx0 = fmaxf(mx0, __shfl_xor_sync(0xffffffffu, mx0, 2));
        mx1 = fmaxf(mx1, __shfl_xor_sync(0xffffffffu, mx1, 1));
        mx1 = fmaxf(mx1, __shfl_xor_sync(0xffffffffu, mx1, 2));

        float mn0 = fmaxf(m0, mx0), mn1 = fmaxf(m1, mx1);
        float al0 = __expf(m0 - mn0), al1 = __expf(m1 - mn1);
        m0 = mn0; m1 = mn1;

        float rs0 = 0.0f, rs1 = 0.0f;
#pragma unroll
        for (int nt = 0; nt < 8; nt++) {
            s[nt][0] = __expf(s[nt][0] - mn0); rs0 += s[nt][0];
            s[nt][1] = __expf(s[nt][1] - mn0); rs0 += s[nt][1];
            s[nt][2] = __expf(s[nt][2] - mn1); rs1 += s[nt][2];
            s[nt][3] = __expf(s[nt][3] - mn1); rs1 += s[nt][3];
        }
        rs0 += __shfl_xor_sync(0xffffffffu, rs0, 1);
        rs0 += __shfl_xor_sync(0xffffffffu, rs0, 2);
        rs1 += __shfl_xor_sync(0xffffffffu, rs1, 1);
        rs1 += __shfl_xor_sync(0xffffffffu, rs1, 2);
        l0 = l0 * al0 + rs0;
        l1 = l1 * al1 + rs1;

#pragma unroll
        for (int nt = 0; nt < 16; nt++) {
            o[nt][0] *= al0; o[nt][1] *= al0;
            o[nt][2] *= al1; o[nt][3] *= al1;
        }

        // ---- P fragments (C-frag -> A-frag), fp16 ----
        uint32_t pa[4][4];
#pragma unroll
        for (int kc = 0; kc < 4; kc++) {
            pa[kc][0] = packh(s[2 * kc][0], s[2 * kc][1]);
            pa[kc][1] = packh(s[2 * kc][2], s[2 * kc][3]);
            pa[kc][2] = packh(s[2 * kc + 1][0], s[2 * kc + 1][1]);
            pa[kc][3] = packh(s[2 * kc + 1][2], s[2 * kc + 1][3]);
        }

        // ---- O += P V  (V via ldmatrix.trans) ----
        const uint32_t vlane = kb + AT_MAT
                               + (uint32_t)(lid & 15) * AT_PITCH
                               + (lid >> 4) * 16;
#pragma unroll
        for (int kc = 0; kc < 4; kc++) {
#pragma unroll
            for (int tt = 0; tt < 8; tt++) {
                uint32_t vh[4];
                uint32_t a_ = vlane + (uint32_t)kc * 16 * AT_PITCH + tt * 32;
                LDMATRIX_X4_TRANS(vh[0], vh[1], vh[2], vh[3], a_);
                MMA_F16(o[2 * tt], pa[kc], vh);
                MMA_F16(o[2 * tt + 1], pa[kc], vh + 2);
            }
        }
        __syncthreads();
    }

    // ---- epilogue: normalize + write fp16 attn output ----
    const float inv0 = 1.0f / l0, inv1 = 1.0f / l1;
    const int b_ = bh >> 4, h_ = bh & 15;
    const int s0 = 128 * qt + 16 * w + (lid >> 2);
    const int s1 = s0 + 8;
    const size_t r0o = ((size_t)b_ * SEQ + s0) * DMODEL + h_ * DHEAD + 2 * (lid & 3);
    const size_t r1o = ((size_t)b_ * SEQ + s1) * DMODEL + h_ * DHEAD + 2 * (lid & 3);
#pragma unroll
    for (int nt = 0; nt < 16; nt++) {
        *(uint32_t*)(g_a + r0o + 8 * nt) = packh(o[nt][0] * inv0, o[nt][1] * inv0);
        *(uint32_t*)(g_a + r1o + 8 * nt) = packh(o[nt][2] * inv1, o[nt][3] * inv1);
    }
#undef ISSUE_KV
}

// ---------------------------------------------------------------------------
extern "C" void kernel_launch(void* const* d_in, const int* in_sizes, int n_in,
                              void* d_out, int out_size)
{
    const float* x     = (const float*)d_in[0];   // [B,S,D]
    const float* Wqkv  = (const float*)d_in[1];   // [D,3D]
    const float* bqkv  = (const float*)d_in[2];   // [3D]
    const float* Wproj = (const float*)d_in[3];   // [D,D]
    const float* bproj = (const float*)d_in[4];   // [D]
    float* out = (float*)d_out;                   // [B,S,D]

    __half *xh, *ah, *wq, *wp;
    cudaGetSymbolAddress((void**)&xh, g_x);
    cudaGetSymbolAddress((void**)&ah, g_a);
    cudaGetSymbolAddress((void**)&wq, g_wqkv);
    cudaGetSymbolAddress((void**)&wp, g_wproj);

    cudaFuncSetAttribute(mma_gemm_kernel<0>,
                         cudaFuncAttributeMaxDynamicSharedMemorySize, GM_SMEM_TOTAL);
    cudaFuncSetAttribute(mma_gemm_kernel<1>,
                         cudaFuncAttributeMaxDynamicSharedMemorySize, GM_SMEM_TOTAL);
    cudaFuncSetAttribute(attn2_kernel,
                         cudaFuncAttributeMaxDynamicSharedMemorySize, AT_SMEM);

    const int M = BATCH * SEQ;   // 4096

    // 1) convert x -> fp16
    {
        int n4 = M * DMODEL / 4;
        convert_kernel<<<(n4 + 255) / 256, 256>>>((const float4*)x, (uint2*)xh, n4);
    }
    // 2) transpose+convert weights -> fp16 [N][K]
    transpose_convert_kernel<<<dim3(3 * DMODEL / 32, DMODEL / 32), dim3(32, 8)>>>(
        Wqkv, wq, DMODEL, 3 * DMODEL);
    transpose_convert_kernel<<<dim3(DMODEL / 32, DMODEL / 32), dim3(32, 8)>>>(
        Wproj, wp, DMODEL, DMODEL);

    // 3) QKV projection (fp16 HMMA) -> fp16 Q/K/V
    mma_gemm_kernel<1><<<dim3(3 * DMODEL / 128, M / 128), 256, GM_SMEM_TOTAL>>>(
        xh, wq, bqkv, nullptr, M, 3 * DMODEL, DMODEL);

    // 4) fp16 HMMA flash attention -> g_a
    attn2_kernel<<<dim3(SEQ / 128, BATCH * NHEAD), 256, AT_SMEM>>>();

    // 5) output projection (fp16 HMMA)
    mma_gemm_kernel<0><<<dim3(DMODEL / 128, M / 128), 256, GM_SMEM_TOTAL>>>(
        ah, wp, bproj, out, M, DMODEL, DMODEL);
}